// round 12
// baseline (speedup 1.0000x reference)
#include <cuda_runtime.h>
#include <cuda_fp16.h>
#include <cstdint>

#define BATCH 8
#define C 128
#define H 128
#define W 128
#define HW (H*W)

// ---------------- scratch (device globals; no allocation allowed) ----------
__device__ float g_y1  [BATCH*C*HW];   // conv1 raw output
__device__ float g_out1[BATCH*C*HW];
__device__ float g_m   [BATCH*C*HW];
__device__ float g_xm  [BATCH*C*HW];   // t * m
__device__ float g_q   [BATCH*C*HW];
__device__ float g_k   [BATCH*C*HW];
__device__ float g_v   [BATCH*C*HW];
__device__ float g_mu  [BATCH*C];
__device__ float g_rsig[BATCH*C];
// fp16 weights packed in per-thread m16n8k16 fragment order
__device__ uint4 g_wH3[3][72*8*32];    // 3x3 convs: [(ks*8+fr)*32+lane]
__device__ uint4 g_wH1[3][8*8*32];     // 1x1 convs

__constant__ int c_di[9] = {-1,-1,-1, 0,0,0, 1,1,1};
__constant__ int c_dj[9] = {-1, 0, 1,-1,0,1,-1,0,1};

__device__ __forceinline__ void mma_f16(float* d, const uint32_t* a, const uint32_t* b) {
    asm volatile(
        "mma.sync.aligned.m16n8k16.row.col.f32.f16.f16.f32 "
        "{%0,%1,%2,%3}, {%4,%5,%6,%7}, {%8,%9}, {%0,%1,%2,%3};"
        : "+f"(d[0]), "+f"(d[1]), "+f"(d[2]), "+f"(d[3])
        : "r"(a[0]), "r"(a[1]), "r"(a[2]), "r"(a[3]), "r"(b[0]), "r"(b[1]));
}
__device__ __forceinline__ uint32_t smem_u32(const void* p) {
    uint32_t a;
    asm("{ .reg .u64 t; cvta.to.shared.u64 t, %1; cvt.u32.u64 %0, t; }"
        : "=r"(a) : "l"(p));
    return a;
}
__device__ __forceinline__ uint32_t pk2(float lo, float hi) {
    __half2 h = __floats2half2_rn(lo, hi);
    return *(uint32_t*)&h;
}
__device__ __forceinline__ float h2lo(uint32_t w) {
    return __low2float(*(__half2*)&w);
}
__device__ __forceinline__ float h2hi(uint32_t w) {
    return __high2float(*(__half2*)&w);
}
#define CP_ASYNC16(dst, src) \
    asm volatile("cp.async.ca.shared.global [%0], [%1], 16;" :: "r"(dst), "l"(src))
#define CP_COMMIT() asm volatile("cp.async.commit_group;")
#define CP_WAIT0()  asm volatile("cp.async.wait_group 0;" ::: "memory")

// ---------------- weight packing (fp16 fragment order) ----------------------
__global__ void pack_weights(const float* __restrict__ w1, const float* __restrict__ w2,
                             const float* __restrict__ wm, const float* __restrict__ wq,
                             const float* __restrict__ wk, const float* __restrict__ wv)
{
    int idx = blockIdx.x * blockDim.x + threadIdx.x;
    int lane = idx & 31;
    int fr   = (idx >> 5) & 7;
    int rest = idx >> 8;
    {
        int ks   = rest % 72;
        int conv = rest / 72;
        if (conv < 3) {
            const float* w = (conv == 0) ? w1 : (conv == 1) ? w2 : wm;
            int m0  = fr*16 + (lane >> 2);
            int kq  = lane & 3;
            int tap = ks >> 3;
            int cb  = (ks & 7) << 4;
            int ca  = cb + 2*kq;
            int cc  = cb + 8 + 2*kq;
            uint4 o;
            o.x = pk2(w[ m0   *1152 + ca*9 + tap], w[ m0   *1152 + (ca+1)*9 + tap]);
            o.y = pk2(w[(m0+8)*1152 + ca*9 + tap], w[(m0+8)*1152 + (ca+1)*9 + tap]);
            o.z = pk2(w[ m0   *1152 + cc*9 + tap], w[ m0   *1152 + (cc+1)*9 + tap]);
            o.w = pk2(w[(m0+8)*1152 + cc*9 + tap], w[(m0+8)*1152 + (cc+1)*9 + tap]);
            g_wH3[conv][(ks*8 + fr)*32 + lane] = o;
        }
    }
    if (idx < 3*8*8*32) {
        int ks  = rest % 8;
        int set = rest / 8;
        const float* w = (set == 0) ? wq : (set == 1) ? wk : wv;
        int m0 = fr*16 + (lane >> 2);
        int kq = lane & 3;
        int cb = ks << 4;
        int ca = cb + 2*kq;
        int cc = cb + 8 + 2*kq;
        uint4 o;
        o.x = pk2(w[ m0   *128 + ca], w[ m0   *128 + ca+1]);
        o.y = pk2(w[(m0+8)*128 + ca], w[(m0+8)*128 + ca+1]);
        o.z = pk2(w[ m0   *128 + cc], w[ m0   *128 + cc+1]);
        o.w = pk2(w[(m0+8)*128 + cc], w[(m0+8)*128 + cc+1]);
        g_wH1[set][(ks*8 + fr)*32 + lane] = o;
    }
}

// ---------------- stats only (mu, rsig per (b,c)) ----------------------------
__global__ void __launch_bounds__(512)
stats_kernel()
{
    int bc = blockIdx.x;
    const float4* p = (const float4*)(g_y1 + (size_t)bc * HW);
    float s = 0.f, sq = 0.f;
    #pragma unroll
    for (int i = 0; i < 8; i++) {
        float4 v = p[threadIdx.x + 512*i];
        s  += (v.x + v.y) + (v.z + v.w);
        sq += v.x*v.x + v.y*v.y + v.z*v.z + v.w*v.w;
    }
    #pragma unroll
    for (int o = 16; o; o >>= 1) {
        s  += __shfl_xor_sync(0xffffffffu, s,  o);
        sq += __shfl_xor_sync(0xffffffffu, sq, o);
    }
    __shared__ float ss[16], sqq[16];
    int wrp = threadIdx.x >> 5;
    if ((threadIdx.x & 31) == 0) { ss[wrp] = s; sqq[wrp] = sq; }
    __syncthreads();
    if (threadIdx.x == 0) {
        float S = 0.f, Q = 0.f;
        #pragma unroll
        for (int i = 0; i < 16; i++) { S += ss[i]; Q += sqq[i]; }
        float mu  = S / (float)HW;
        float var = Q / (float)HW - mu*mu;
        g_mu[bc]   = mu;
        g_rsig[bc] = rsqrtf(var + 1e-5f);
    }
}

// ---------------- fp16 3x3 conv core (B-stationary tile, SW pipelined) ------
#define TPIX 204
#define TSTRIDE 68
#define CONV_SMEM (TPIX*TSTRIDE*4)     // 55488 B

__device__ __forceinline__ void conv_pass(const uint32_t* tile, const uint4* wA,
                                          int mw, int nw, int lane,
                                          float acc[4][4][4])
{
    const int q = lane & 3, g = lane >> 2;
    uint4 aN[4];
    #pragma unroll
    for (int i = 0; i < 4; i++)
        aN[i] = wA[(mw*4 + i)*32 + lane];

    uint32_t bfN[4][2];
    {
        int pxb = (nw + c_di[0] + 1)*34 + c_dj[0] + 1 + g;
        #pragma unroll
        for (int j = 0; j < 4; j++) {
            int off = (pxb + j*8)*TSTRIDE + q;
            bfN[j][0] = tile[off];
            bfN[j][1] = tile[off + 4];
        }
    }

    const int NR = 72;
    #pragma unroll 8
    for (int r = 0; r < NR; r++) {
        uint4 aC[4];
        uint32_t bf[4][2];
        #pragma unroll
        for (int i = 0; i < 4; i++) aC[i] = aN[i];
        #pragma unroll
        for (int j = 0; j < 4; j++) { bf[j][0] = bfN[j][0]; bf[j][1] = bfN[j][1]; }
        if (r + 1 < NR) {
            const uint4* src = wA + (size_t)(r + 1)*256;
            #pragma unroll
            for (int i = 0; i < 4; i++)
                aN[i] = src[(mw*4 + i)*32 + lane];
            int tap = (r + 1) >> 3;
            int cw  = (((r + 1) & 7) << 3) + q;
            int pxb = (nw + c_di[tap] + 1)*34 + c_dj[tap] + 1 + g;
            #pragma unroll
            for (int j = 0; j < 4; j++) {
                int off = (pxb + j*8)*TSTRIDE + cw;
                bfN[j][0] = tile[off];
                bfN[j][1] = tile[off + 4];
            }
        }
        #pragma unroll
        for (int i = 0; i < 4; i++)
            #pragma unroll
            for (int j = 0; j < 4; j++)
                mma_f16(acc[i][j], (const uint32_t*)&aC[i], bf[j]);
    }
}

// ---------------- conv1: raw x -> y1 -----------------------------------------
__global__ void __launch_bounds__(256, 2)
conv1_kernel(const float* __restrict__ in, const float* __restrict__ bias)
{
    extern __shared__ uint32_t tile[];

    const int tid  = threadIdx.x;
    const int lane = tid & 31, wid = tid >> 5;
    const int mw = wid >> 2, nw = wid & 3;
    const int b  = blockIdx.y;
    const int h0 = (blockIdx.x >> 2) << 2;
    const int w0 = (blockIdx.x & 3) << 5;

    #pragma unroll 4
    for (int pp = 0; pp < 51; pp++) {
        int idx  = pp*256 + tid;
        int pair = idx / 204;
        int pix  = idx - pair*204;
        int pr = pix / 34, pc = pix - pr*34;
        int ih = h0 + pr - 1, iw = w0 + pc - 1;
        float v0 = 0.f, v1 = 0.f;
        if (((unsigned)ih < (unsigned)H) && ((unsigned)iw < (unsigned)W)) {
            const float* s = in + ((size_t)(b*C + 2*pair) << 14) + (size_t)ih*W + iw;
            v0 = s[0];
            v1 = s[(size_t)1 << 14];
        }
        tile[pix*TSTRIDE + pair] = pk2(v0, v1);
    }
    __syncthreads();

    float acc[4][4][4];
    #pragma unroll
    for (int i = 0; i < 4; i++)
        #pragma unroll
        for (int j = 0; j < 4; j++)
            #pragma unroll
            for (int r = 0; r < 4; r++) acc[i][j][r] = 0.f;

    conv_pass(tile, g_wH3[0], mw, nw, lane, acc);

    const int q = lane & 3, g = lane >> 2;
    #pragma unroll
    for (int i = 0; i < 4; i++) {
        int m0 = mw*64 + i*16 + g;
        float bb0 = bias[m0], bb1 = bias[m0 + 8];
        size_t ob = ((size_t)(b*C + m0) << 14) + (size_t)(h0 + nw)*W + w0;
        #pragma unroll
        for (int j = 0; j < 4; j++) {
            int co = j*8 + q*2;
            *(float2*)(g_y1 + ob + co) =
                make_float2(acc[i][j][0] + bb0, acc[i][j][1] + bb0);
            *(float2*)(g_y1 + ob + (8 << 14) + co) =
                make_float2(acc[i][j][2] + bb1, acc[i][j][3] + bb1);
        }
    }
}

// ---------------- merged conv2 + mask: one staged t-tile, two passes ---------
__global__ void __launch_bounds__(256, 2)
conv2m_kernel(const float* __restrict__ b2, const float* __restrict__ bm)
{
    extern __shared__ uint32_t tile[];

    const int tid  = threadIdx.x;
    const int lane = tid & 31, wid = tid >> 5;
    const int mw = wid >> 2, nw = wid & 3;
    const int b  = blockIdx.y;
    const int h0 = (blockIdx.x >> 2) << 2;
    const int w0 = (blockIdx.x & 3) << 5;
    const int q = lane & 3, g = lane >> 2;

    const float* mup = g_mu   + b*C;
    const float* rsp = g_rsig + b*C;

    // stage t = leaky(norm(y1)) as fp16
    #pragma unroll 4
    for (int pp = 0; pp < 51; pp++) {
        int idx  = pp*256 + tid;
        int pair = idx / 204;
        int pix  = idx - pair*204;
        int pr = pix / 34, pc = pix - pr*34;
        int ih = h0 + pr - 1, iw = w0 + pc - 1;
        float v0 = 0.f, v1 = 0.f;
        if (((unsigned)ih < (unsigned)H) && ((unsigned)iw < (unsigned)W)) {
            const float* s = g_y1 + ((size_t)(b*C + 2*pair) << 14) + (size_t)ih*W + iw;
            float y0 = s[0], y1v = s[(size_t)1 << 14];
            float t0 = (y0  - mup[2*pair])   * rsp[2*pair];
            float t1 = (y1v - mup[2*pair+1]) * rsp[2*pair+1];
            v0 = (t0 < 0.f) ? 0.2f*t0 : t0;
            v1 = (t1 < 0.f) ? 0.2f*t1 : t1;
        }
        tile[pix*TSTRIDE + pair] = pk2(v0, v1);
    }
    __syncthreads();

    float acc[4][4][4];

    // ---- pass 1: conv2 -> out1 ----
    #pragma unroll
    for (int i = 0; i < 4; i++)
        #pragma unroll
        for (int j = 0; j < 4; j++)
            #pragma unroll
            for (int r = 0; r < 4; r++) acc[i][j][r] = 0.f;
    conv_pass(tile, g_wH3[1], mw, nw, lane, acc);
    #pragma unroll
    for (int i = 0; i < 4; i++) {
        int m0 = mw*64 + i*16 + g;
        float bb0 = b2[m0], bb1 = b2[m0 + 8];
        size_t ob = ((size_t)(b*C + m0) << 14) + (size_t)(h0 + nw)*W + w0;
        #pragma unroll
        for (int j = 0; j < 4; j++) {
            int co = j*8 + q*2;
            *(float2*)(g_out1 + ob + co) =
                make_float2(acc[i][j][0] + bb0, acc[i][j][1] + bb0);
            *(float2*)(g_out1 + ob + (8 << 14) + co) =
                make_float2(acc[i][j][2] + bb1, acc[i][j][3] + bb1);
        }
    }

    // ---- pass 2: mask -> m, xm = t*m (t from staged fp16 tile) ----
    #pragma unroll
    for (int i = 0; i < 4; i++)
        #pragma unroll
        for (int j = 0; j < 4; j++)
            #pragma unroll
            for (int r = 0; r < 4; r++) acc[i][j][r] = 0.f;
    conv_pass(tile, g_wH3[2], mw, nw, lane, acc);
    #pragma unroll
    for (int i = 0; i < 4; i++) {
        int m0 = mw*64 + i*16 + g;
        int mh = m0 >> 1;
        int par = m0 & 1;
        float bb0 = bm[m0], bb1 = bm[m0 + 8];
        size_t ob = ((size_t)(b*C + m0) << 14) + (size_t)(h0 + nw)*W + w0;
        #pragma unroll
        for (int j = 0; j < 4; j++) {
            int co = j*8 + q*2;
            int pix = (nw + 1)*34 + co + 1;
            uint32_t wa0 = tile[ pix     *TSTRIDE + mh];
            uint32_t wa1 = tile[(pix + 1)*TSTRIDE + mh];
            uint32_t wb0 = tile[ pix     *TSTRIDE + mh + 4];
            uint32_t wb1 = tile[(pix + 1)*TSTRIDE + mh + 4];
            float t00 = par ? h2hi(wa0) : h2lo(wa0);
            float t01 = par ? h2hi(wa1) : h2lo(wa1);
            float t10 = par ? h2hi(wb0) : h2lo(wb0);
            float t11 = par ? h2hi(wb1) : h2lo(wb1);
            float s0 = 1.f/(1.f + __expf(-(acc[i][j][0] + bb0)));
            float s1 = 1.f/(1.f + __expf(-(acc[i][j][1] + bb0)));
            float s2 = 1.f/(1.f + __expf(-(acc[i][j][2] + bb1)));
            float s3 = 1.f/(1.f + __expf(-(acc[i][j][3] + bb1)));
            *(float2*)(g_m + ob + co)             = make_float2(s0, s1);
            *(float2*)(g_m + ob + (8 << 14) + co) = make_float2(s2, s3);
            *(float2*)(g_xm + ob + co)             = make_float2(s0*t00, s1*t01);
            *(float2*)(g_xm + ob + (8 << 14) + co) = make_float2(s2*t10, s3*t11);
        }
    }
}

// ---------------- merged q/k/v 1x1 GEMM (shared fp16 B staging) --------------
#define BP 136
__global__ void __launch_bounds__(256, 2)
conv_qkv(const float* __restrict__ bq, const float* __restrict__ bk,
         const float* __restrict__ bv_)
{
    __shared__ uint32_t Bsq[8][8*BP];
    __shared__ uint4    Asq[2][256];

    const int tid  = threadIdx.x;
    const int lane = tid & 31, wid = tid >> 5;
    const int mw = wid >> 2, nw = wid & 3;
    const int b  = blockIdx.y;
    const int h0 = (blockIdx.x >> 2) << 2;
    const int w0 = (blockIdx.x & 3) << 5;

    const int sub  = tid >> 7;
    const int nn   = tid & 127;
    const int prow = nn >> 5, pcol = nn & 31;

    const uint32_t aBase = smem_u32(&Asq[0][0]);
    auto cpA = [&](const uint4* wA, int r, int buf) {
        CP_ASYNC16(aBase + ((buf*256 + tid) << 4), wA + (size_t)r*256 + tid);
        CP_COMMIT();
    };

    {
        const float* src0 = (const float*)g_xm + ((size_t)(b*C) << 14)
                          + (size_t)(h0 + prow)*W + (w0 + pcol);
        #pragma unroll
        for (int ks = 0; ks < 8; ks++) {
            const float* src = src0 + ((size_t)(ks*16 + sub*8) << 14);
            float vb[8];
            #pragma unroll
            for (int j = 0; j < 8; j++)
                vb[j] = src[(size_t)j << 14];
            #pragma unroll
            for (int p = 0; p < 4; p++)
                Bsq[ks][(sub*4 + p)*BP + nn] = pk2(vb[2*p], vb[2*p + 1]);
        }
    }

    for (int set = 0; set < 3; set++) {
        const uint4* wA = g_wH1[set];
        const float* bias = (set == 0) ? bq : (set == 1) ? bk : bv_;
        float* out = (set == 0) ? g_q : (set == 1) ? g_k : g_v;

        float acc[4][4][4];
        #pragma unroll
        for (int i = 0; i < 4; i++)
            #pragma unroll
            for (int j = 0; j < 4; j++)
                #pragma unroll
                for (int r = 0; r < 4; r++) acc[i][j][r] = 0.f;

        cpA(wA, 0, 0);
        CP_WAIT0();
        __syncthreads();

        for (int r = 0; r < 8; r++) {
            int buf = r & 1;
            if (r + 1 < 8) cpA(wA, r + 1, buf ^ 1);
            uint4 af[4];
            #pragma unroll
            for (int i = 0; i < 4; i++)
                af[i] = Asq[buf][(mw*4 + i)*32 + lane];
            uint32_t bf[4][2];
            const int q = lane & 3;
            #pragma unroll
            for (int j = 0; j < 4; j++) {
                int n = nw*32 + j*8 + (lane >> 2);
                bf[j][0] = Bsq[r][ q     *BP + n];
                bf[j][1] = Bsq[r][(4 + q)*BP + n];
            }
            #pragma unroll
            for (int i = 0; i < 4; i++)
                #pragma unroll
                for (int j = 0; j < 4; j++)
                    mma_f16(acc[i][j], (const uint32_t*)&af[i], bf[j]);
            if (r + 1 < 8) {
                CP_WAIT0();
                __syncthreads();
            }
        }

        #pragma unroll
        for (int i = 0; i < 4; i++) {
            int m0 = mw*64 + i*16 + (lane >> 2);
            float bb0 = bias[m0], bb1 = bias[m0 + 8];
            size_t ob = ((size_t)(b*C + m0) << 14) + (size_t)(h0 + nw)*W + w0;
            #pragma unroll
            for (int j = 0; j < 4; j++) {
                int co = j*8 + (lane & 3)*2;
                *(float2*)(out + ob + co) =
                    make_float2(acc[i][j][0] + bb0, acc[i][j][1] + bb0);
                *(float2*)(out + ob + (8 << 14) + co) =
                    make_float2(acc[i][j][2] + bb1, acc[i][j][3] + bb1);
            }
        }
        __syncthreads();
    }
}

// ---------------- local 3x3 attention + blend + residual --------------------
// 8-way channel split (16 ch each), 1 row/CTA, shuffle edge taps, unroll 4.
__global__ void __launch_bounds__(256)
attn_kernel(const float* __restrict__ x, const float* __restrict__ k_b,
            const float* __restrict__ v_b, float* __restrict__ out)
{
    __shared__ float att[8][32][37];

    const int b    = blockIdx.y;
    const int tid  = threadIdx.x;
    const int cg   = tid >> 5;
    const int lane = tid & 31;
    const int h    = blockIdx.x;
    const int wq   = lane*4;
    const size_t bbase = (size_t)b*C*HW;
    const int poff = h*W + wq;
    const int c0 = cg*16;

    float sims[9][4];
    #pragma unroll
    for (int o = 0; o < 9; o++)
        #pragma unroll
        for (int p = 0; p < 4; p++) sims[o][p] = 0.f;

    #pragma unroll 4
    for (int ci = 0; ci < 16; ci++) {
        int c = c0 + ci;
        const float* kp = g_k + bbase + ((size_t)c << 14);
        float kbv = __ldg(k_b + c);
        float4 qv = *(const float4*)(g_q + bbase + ((size_t)c << 14) + poff);
        float q[4] = {qv.x, qv.y, qv.z, qv.w};
        #pragma unroll
        for (int dr = 0; dr < 3; dr++) {
            int hh = h + dr - 1;
            bool rok = ((unsigned)hh < (unsigned)H);
            float4 mid = rok ? *(const float4*)(kp + hh*W + wq)
                             : make_float4(kbv, kbv, kbv, kbv);
            float lf = __shfl_up_sync(0xffffffffu, mid.w, 1);
            if (lane == 0)  lf = kbv;
            float rt = __shfl_down_sync(0xffffffffu, mid.x, 1);
            if (lane == 31) rt = kbv;
            float val[6] = {lf, mid.x, mid.y, mid.z, mid.w, rt};
            #pragma unroll
            for (int dj = 0; dj < 3; dj++)
                #pragma unroll
                for (int p = 0; p < 4; p++)
                    sims[dr*3 + dj][p] = fmaf(q[p], val[p + dj], sims[dr*3 + dj][p]);
        }
    }

    #pragma unroll
    for (int o = 0; o < 9; o++)
        #pragma unroll
        for (int p = 0; p < 4; p++)
            att[cg][lane][o*4 + p] = sims[o][p];
    __syncthreads();

    #pragma unroll
    for (int o = 0; o < 9; o++) {
        #pragma unroll
        for (int p = 0; p < 4; p++) {
            float s = 0.f;
            #pragma unroll
            for (int gr = 0; gr < 8; gr++)
                s += att[gr][lane][o*4 + p];
            sims[o][p] = s;
        }
    }
    #pragma unroll
    for (int p = 0; p < 4; p++) {
        float mx = sims[0][p];
        #pragma unroll
        for (int o = 1; o < 9; o++) mx = fmaxf(mx, sims[o][p]);
        float se = 0.f;
        #pragma unroll
        for (int o = 0; o < 9; o++) { sims[o][p] = __expf(sims[o][p] - mx); se += sims[o][p]; }
        float inv = 1.f / se;
        #pragma unroll
        for (int o = 0; o < 9; o++) sims[o][p] *= inv;
    }

    #pragma unroll 4
    for (int ci = 0; ci < 16; ci++) {
        int c = c0 + ci;
        const float* vp = g_v + bbase + ((size_t)c << 14);
        float vbv = __ldg(v_b + c);
        float o2[4] = {0.f, 0.f, 0.f, 0.f};
        #pragma unroll
        for (int dr = 0; dr < 3; dr++) {
            int hh = h + dr - 1;
            bool rok = ((unsigned)hh < (unsigned)H);
            float4 mid = rok ? *(const float4*)(vp + hh*W + wq)
                             : make_float4(vbv, vbv, vbv, vbv);
            float lf = __shfl_up_sync(0xffffffffu, mid.w, 1);
            if (lane == 0)  lf = vbv;
            float rt = __shfl_down_sync(0xffffffffu, mid.x, 1);
            if (lane == 31) rt = vbv;
            float val[6] = {lf, mid.x, mid.y, mid.z, mid.w, rt};
            #pragma unroll
            for (int dj = 0; dj < 3; dj++)
                #pragma unroll
                for (int p = 0; p < 4; p++)
                    o2[p] = fmaf(sims[dr*3 + dj][p], val[p + dj], o2[p]);
        }
        size_t idx = bbase + ((size_t)c << 14) + poff;
        float4 mv = *(const float4*)(g_m    + idx);
        float4 o1 = *(const float4*)(g_out1 + idx);
        float4 xv = *(const float4*)(x      + idx);
        float4 ov;
        ov.x = xv.x + o1.x*mv.x + (1.f - mv.x)*o2[0];
        ov.y = xv.y + o1.y*mv.y + (1.f - mv.y)*o2[1];
        ov.z = xv.z + o1.z*mv.z + (1.f - mv.z)*o2[2];
        ov.w = xv.w + o1.w*mv.w + (1.f - mv.w)*o2[3];
        *(float4*)(out + idx) = ov;
    }
}

// ---------------- launch ----------------------------------------------------
extern "C" void kernel_launch(void* const* d_in, const int* in_sizes, int n_in,
                              void* d_out, int out_size)
{
    const float* x  = (const float*)d_in[0];
    const float* w1 = (const float*)d_in[1];
    const float* b1 = (const float*)d_in[2];
    const float* w2 = (const float*)d_in[3];
    const float* b2 = (const float*)d_in[4];
    const float* wm = (const float*)d_in[5];
    const float* bm = (const float*)d_in[6];
    const float* wq = (const float*)d_in[7];
    const float* bq = (const float*)d_in[8];
    const float* wk = (const float*)d_in[9];
    const float* bk = (const float*)d_in[10];
    const float* wv = (const float*)d_in[11];
    const float* bv = (const float*)d_in[12];
    float* out = (float*)d_out;

    cudaFuncSetAttribute(conv1_kernel,  cudaFuncAttributeMaxDynamicSharedMemorySize, CONV_SMEM);
    cudaFuncSetAttribute(conv2m_kernel, cudaFuncAttributeMaxDynamicSharedMemorySize, CONV_SMEM);

    pack_weights<<<216, 256>>>(w1, w2, wm, wq, wk, wv);

    dim3 gc(128, BATCH);
    conv1_kernel<<<gc, 256, CONV_SMEM>>>(x, b1);
    stats_kernel<<<BATCH*C, 512>>>();
    conv2m_kernel<<<gc, 256, CONV_SMEM>>>(b2, bm);
    conv_qkv<<<gc, 256>>>(bq, bk, bv);

    dim3 ga(H, BATCH);
    attn_kernel<<<ga, 256>>>(x, bk, bv, out);
}

// round 13
// speedup vs baseline: 1.1180x; 1.1180x over previous
#include <cuda_runtime.h>
#include <cuda_fp16.h>
#include <cstdint>

#define BATCH 8
#define C 128
#define H 128
#define W 128
#define HW (H*W)

// ---------------- scratch (device globals; no allocation allowed) ----------
__device__ float  g_y1  [BATCH*C*HW];   // conv1 raw output
__device__ float  g_out1[BATCH*C*HW];
__device__ float  g_m   [BATCH*C*HW];
__device__ float  g_xm  [BATCH*C*HW];   // t * m
__device__ __half g_q   [BATCH*C*HW];
__device__ __half g_k   [BATCH*C*HW];
__device__ __half g_v   [BATCH*C*HW];
__device__ float  g_mu  [BATCH*C];
__device__ float  g_rsig[BATCH*C];
// fp16 weights packed in per-thread m16n8k16 fragment order
__device__ uint4 g_wH3[3][72*8*32];    // 3x3 convs: [(ks*8+fr)*32+lane]
__device__ uint4 g_wH1[3][8*8*32];     // 1x1 convs

__constant__ int c_di[9] = {-1,-1,-1, 0,0,0, 1,1,1};
__constant__ int c_dj[9] = {-1, 0, 1,-1,0,1,-1,0,1};

__device__ __forceinline__ void mma_f16(float* d, const uint32_t* a, const uint32_t* b) {
    asm volatile(
        "mma.sync.aligned.m16n8k16.row.col.f32.f16.f16.f32 "
        "{%0,%1,%2,%3}, {%4,%5,%6,%7}, {%8,%9}, {%0,%1,%2,%3};"
        : "+f"(d[0]), "+f"(d[1]), "+f"(d[2]), "+f"(d[3])
        : "r"(a[0]), "r"(a[1]), "r"(a[2]), "r"(a[3]), "r"(b[0]), "r"(b[1]));
}
__device__ __forceinline__ uint32_t smem_u32(const void* p) {
    uint32_t a;
    asm("{ .reg .u64 t; cvta.to.shared.u64 t, %1; cvt.u32.u64 %0, t; }"
        : "=r"(a) : "l"(p));
    return a;
}
__device__ __forceinline__ uint32_t pk2(float lo, float hi) {
    __half2 h = __floats2half2_rn(lo, hi);
    return *(uint32_t*)&h;
}
__device__ __forceinline__ float h2lo(uint32_t w) {
    return __low2float(*(__half2*)&w);
}
__device__ __forceinline__ float h2hi(uint32_t w) {
    return __high2float(*(__half2*)&w);
}
#define CP_ASYNC16(dst, src) \
    asm volatile("cp.async.ca.shared.global [%0], [%1], 16;" :: "r"(dst), "l"(src))
#define CP_COMMIT() asm volatile("cp.async.commit_group;")
#define CP_WAIT0()  asm volatile("cp.async.wait_group 0;" ::: "memory")

// ---------------- weight packing (fp16 fragment order) ----------------------
__global__ void pack_weights(const float* __restrict__ w1, const float* __restrict__ w2,
                             const float* __restrict__ wm, const float* __restrict__ wq,
                             const float* __restrict__ wk, const float* __restrict__ wv)
{
    int idx = blockIdx.x * blockDim.x + threadIdx.x;
    int lane = idx & 31;
    int fr   = (idx >> 5) & 7;
    int rest = idx >> 8;
    {
        int ks   = rest % 72;
        int conv = rest / 72;
        if (conv < 3) {
            const float* w = (conv == 0) ? w1 : (conv == 1) ? w2 : wm;
            int m0  = fr*16 + (lane >> 2);
            int kq  = lane & 3;
            int tap = ks >> 3;
            int cb  = (ks & 7) << 4;
            int ca  = cb + 2*kq;
            int cc  = cb + 8 + 2*kq;
            uint4 o;
            o.x = pk2(w[ m0   *1152 + ca*9 + tap], w[ m0   *1152 + (ca+1)*9 + tap]);
            o.y = pk2(w[(m0+8)*1152 + ca*9 + tap], w[(m0+8)*1152 + (ca+1)*9 + tap]);
            o.z = pk2(w[ m0   *1152 + cc*9 + tap], w[ m0   *1152 + (cc+1)*9 + tap]);
            o.w = pk2(w[(m0+8)*1152 + cc*9 + tap], w[(m0+8)*1152 + (cc+1)*9 + tap]);
            g_wH3[conv][(ks*8 + fr)*32 + lane] = o;
        }
    }
    if (idx < 3*8*8*32) {
        int ks  = rest % 8;
        int set = rest / 8;
        const float* w = (set == 0) ? wq : (set == 1) ? wk : wv;
        int m0 = fr*16 + (lane >> 2);
        int kq = lane & 3;
        int cb = ks << 4;
        int ca = cb + 2*kq;
        int cc = cb + 8 + 2*kq;
        uint4 o;
        o.x = pk2(w[ m0   *128 + ca], w[ m0   *128 + ca+1]);
        o.y = pk2(w[(m0+8)*128 + ca], w[(m0+8)*128 + ca+1]);
        o.z = pk2(w[ m0   *128 + cc], w[ m0   *128 + cc+1]);
        o.w = pk2(w[(m0+8)*128 + cc], w[(m0+8)*128 + cc+1]);
        g_wH1[set][(ks*8 + fr)*32 + lane] = o;
    }
}

// ---------------- stats only (mu, rsig per (b,c)) ----------------------------
__global__ void __launch_bounds__(512)
stats_kernel()
{
    int bc = blockIdx.x;
    const float4* p = (const float4*)(g_y1 + (size_t)bc * HW);
    float s = 0.f, sq = 0.f;
    #pragma unroll
    for (int i = 0; i < 8; i++) {
        float4 v = p[threadIdx.x + 512*i];
        s  += (v.x + v.y) + (v.z + v.w);
        sq += v.x*v.x + v.y*v.y + v.z*v.z + v.w*v.w;
    }
    #pragma unroll
    for (int o = 16; o; o >>= 1) {
        s  += __shfl_xor_sync(0xffffffffu, s,  o);
        sq += __shfl_xor_sync(0xffffffffu, sq, o);
    }
    __shared__ float ss[16], sqq[16];
    int wrp = threadIdx.x >> 5;
    if ((threadIdx.x & 31) == 0) { ss[wrp] = s; sqq[wrp] = sq; }
    __syncthreads();
    if (threadIdx.x == 0) {
        float S = 0.f, Q = 0.f;
        #pragma unroll
        for (int i = 0; i < 16; i++) { S += ss[i]; Q += sqq[i]; }
        float mu  = S / (float)HW;
        float var = Q / (float)HW - mu*mu;
        g_mu[bc]   = mu;
        g_rsig[bc] = rsqrtf(var + 1e-5f);
    }
}

// ---------------- fp16 3x3 conv core (B-stationary tile) ---------------------
#define TPIX 204
#define TSTRIDE 68
#define CONV_SMEM (TPIX*TSTRIDE*4)     // 55488 B

__device__ __forceinline__ void conv_pass(const uint32_t* tile, const uint4* wA,
                                          int mw, int nw, int lane,
                                          float acc[4][4][4])
{
    const int q = lane & 3, g = lane >> 2;
    uint4 aN[4];
    #pragma unroll
    for (int i = 0; i < 4; i++)
        aN[i] = wA[(mw*4 + i)*32 + lane];

    const int NR = 72;
    for (int r = 0; r < NR; r++) {
        uint4 aC[4];
        #pragma unroll
        for (int i = 0; i < 4; i++) aC[i] = aN[i];
        if (r + 1 < NR) {
            const uint4* src = wA + (size_t)(r + 1)*256;
            #pragma unroll
            for (int i = 0; i < 4; i++)
                aN[i] = src[(mw*4 + i)*32 + lane];
        }
        int tap = r >> 3;
        int cw  = ((r & 7) << 3) + q;
        int pxb = (nw + c_di[tap] + 1)*34 + c_dj[tap] + 1 + g;
        uint32_t bf[4][2];
        #pragma unroll
        for (int j = 0; j < 4; j++) {
            int off = (pxb + j*8)*TSTRIDE + cw;
            bf[j][0] = tile[off];
            bf[j][1] = tile[off + 4];
        }
        #pragma unroll
        for (int i = 0; i < 4; i++)
            #pragma unroll
            for (int j = 0; j < 4; j++)
                mma_f16(acc[i][j], (const uint32_t*)&aC[i], bf[j]);
    }
}

// ---------------- conv1: raw x -> y1 -----------------------------------------
__global__ void __launch_bounds__(256, 2)
conv1_kernel(const float* __restrict__ in, const float* __restrict__ bias)
{
    extern __shared__ uint32_t tile[];

    const int tid  = threadIdx.x;
    const int lane = tid & 31, wid = tid >> 5;
    const int mw = wid >> 2, nw = wid & 3;
    const int b  = blockIdx.y;
    const int h0 = (blockIdx.x >> 2) << 2;
    const int w0 = (blockIdx.x & 3) << 5;

    #pragma unroll 4
    for (int pp = 0; pp < 51; pp++) {
        int idx  = pp*256 + tid;
        int pair = idx / 204;
        int pix  = idx - pair*204;
        int pr = pix / 34, pc = pix - pr*34;
        int ih = h0 + pr - 1, iw = w0 + pc - 1;
        float v0 = 0.f, v1 = 0.f;
        if (((unsigned)ih < (unsigned)H) && ((unsigned)iw < (unsigned)W)) {
            const float* s = in + ((size_t)(b*C + 2*pair) << 14) + (size_t)ih*W + iw;
            v0 = s[0];
            v1 = s[(size_t)1 << 14];
        }
        tile[pix*TSTRIDE + pair] = pk2(v0, v1);
    }
    __syncthreads();

    float acc[4][4][4];
    #pragma unroll
    for (int i = 0; i < 4; i++)
        #pragma unroll
        for (int j = 0; j < 4; j++)
            #pragma unroll
            for (int r = 0; r < 4; r++) acc[i][j][r] = 0.f;

    conv_pass(tile, g_wH3[0], mw, nw, lane, acc);

    const int q = lane & 3, g = lane >> 2;
    #pragma unroll
    for (int i = 0; i < 4; i++) {
        int m0 = mw*64 + i*16 + g;
        float bb0 = bias[m0], bb1 = bias[m0 + 8];
        size_t ob = ((size_t)(b*C + m0) << 14) + (size_t)(h0 + nw)*W + w0;
        #pragma unroll
        for (int j = 0; j < 4; j++) {
            int co = j*8 + q*2;
            *(float2*)(g_y1 + ob + co) =
                make_float2(acc[i][j][0] + bb0, acc[i][j][1] + bb0);
            *(float2*)(g_y1 + ob + (8 << 14) + co) =
                make_float2(acc[i][j][2] + bb1, acc[i][j][3] + bb1);
        }
    }
}

// ---------------- merged conv2 + mask: one staged t-tile, two passes ---------
__global__ void __launch_bounds__(256, 2)
conv2m_kernel(const float* __restrict__ b2, const float* __restrict__ bm)
{
    extern __shared__ uint32_t tile[];

    const int tid  = threadIdx.x;
    const int lane = tid & 31, wid = tid >> 5;
    const int mw = wid >> 2, nw = wid & 3;
    const int b  = blockIdx.y;
    const int h0 = (blockIdx.x >> 2) << 2;
    const int w0 = (blockIdx.x & 3) << 5;
    const int q = lane & 3, g = lane >> 2;

    const float* mup = g_mu   + b*C;
    const float* rsp = g_rsig + b*C;

    // stage t = leaky(norm(y1)) as fp16
    #pragma unroll 4
    for (int pp = 0; pp < 51; pp++) {
        int idx  = pp*256 + tid;
        int pair = idx / 204;
        int pix  = idx - pair*204;
        int pr = pix / 34, pc = pix - pr*34;
        int ih = h0 + pr - 1, iw = w0 + pc - 1;
        float v0 = 0.f, v1 = 0.f;
        if (((unsigned)ih < (unsigned)H) && ((unsigned)iw < (unsigned)W)) {
            const float* s = g_y1 + ((size_t)(b*C + 2*pair) << 14) + (size_t)ih*W + iw;
            float y0 = s[0], y1v = s[(size_t)1 << 14];
            float t0 = (y0  - mup[2*pair])   * rsp[2*pair];
            float t1 = (y1v - mup[2*pair+1]) * rsp[2*pair+1];
            v0 = (t0 < 0.f) ? 0.2f*t0 : t0;
            v1 = (t1 < 0.f) ? 0.2f*t1 : t1;
        }
        tile[pix*TSTRIDE + pair] = pk2(v0, v1);
    }
    __syncthreads();

    float acc[4][4][4];

    // ---- pass 1: conv2 -> out1 ----
    #pragma unroll
    for (int i = 0; i < 4; i++)
        #pragma unroll
        for (int j = 0; j < 4; j++)
            #pragma unroll
            for (int r = 0; r < 4; r++) acc[i][j][r] = 0.f;
    conv_pass(tile, g_wH3[1], mw, nw, lane, acc);
    #pragma unroll
    for (int i = 0; i < 4; i++) {
        int m0 = mw*64 + i*16 + g;
        float bb0 = b2[m0], bb1 = b2[m0 + 8];
        size_t ob = ((size_t)(b*C + m0) << 14) + (size_t)(h0 + nw)*W + w0;
        #pragma unroll
        for (int j = 0; j < 4; j++) {
            int co = j*8 + q*2;
            *(float2*)(g_out1 + ob + co) =
                make_float2(acc[i][j][0] + bb0, acc[i][j][1] + bb0);
            *(float2*)(g_out1 + ob + (8 << 14) + co) =
                make_float2(acc[i][j][2] + bb1, acc[i][j][3] + bb1);
        }
    }

    // ---- pass 2: mask -> m, xm = t*m (t from staged fp16 tile) ----
    #pragma unroll
    for (int i = 0; i < 4; i++)
        #pragma unroll
        for (int j = 0; j < 4; j++)
            #pragma unroll
            for (int r = 0; r < 4; r++) acc[i][j][r] = 0.f;
    conv_pass(tile, g_wH3[2], mw, nw, lane, acc);
    #pragma unroll
    for (int i = 0; i < 4; i++) {
        int m0 = mw*64 + i*16 + g;
        int mh = m0 >> 1;
        int par = m0 & 1;
        float bb0 = bm[m0], bb1 = bm[m0 + 8];
        size_t ob = ((size_t)(b*C + m0) << 14) + (size_t)(h0 + nw)*W + w0;
        #pragma unroll
        for (int j = 0; j < 4; j++) {
            int co = j*8 + q*2;
            int pix = (nw + 1)*34 + co + 1;
            uint32_t wa0 = tile[ pix     *TSTRIDE + mh];
            uint32_t wa1 = tile[(pix + 1)*TSTRIDE + mh];
            uint32_t wb0 = tile[ pix     *TSTRIDE + mh + 4];
            uint32_t wb1 = tile[(pix + 1)*TSTRIDE + mh + 4];
            float t00 = par ? h2hi(wa0) : h2lo(wa0);
            float t01 = par ? h2hi(wa1) : h2lo(wa1);
            float t10 = par ? h2hi(wb0) : h2lo(wb0);
            float t11 = par ? h2hi(wb1) : h2lo(wb1);
            float s0 = 1.f/(1.f + __expf(-(acc[i][j][0] + bb0)));
            float s1 = 1.f/(1.f + __expf(-(acc[i][j][1] + bb0)));
            float s2 = 1.f/(1.f + __expf(-(acc[i][j][2] + bb1)));
            float s3 = 1.f/(1.f + __expf(-(acc[i][j][3] + bb1)));
            *(float2*)(g_m + ob + co)             = make_float2(s0, s1);
            *(float2*)(g_m + ob + (8 << 14) + co) = make_float2(s2, s3);
            *(float2*)(g_xm + ob + co)             = make_float2(s0*t00, s1*t01);
            *(float2*)(g_xm + ob + (8 << 14) + co) = make_float2(s2*t10, s3*t11);
        }
    }
}

// ---------------- merged q/k/v 1x1 GEMM (fp16 outputs) -----------------------
#define BP 136
__global__ void __launch_bounds__(256, 2)
conv_qkv(const float* __restrict__ bq, const float* __restrict__ bk,
         const float* __restrict__ bv_)
{
    __shared__ uint32_t Bsq[8][8*BP];
    __shared__ uint4    Asq[2][256];

    const int tid  = threadIdx.x;
    const int lane = tid & 31, wid = tid >> 5;
    const int mw = wid >> 2, nw = wid & 3;
    const int b  = blockIdx.y;
    const int h0 = (blockIdx.x >> 2) << 2;
    const int w0 = (blockIdx.x & 3) << 5;

    const int sub  = tid >> 7;
    const int nn   = tid & 127;
    const int prow = nn >> 5, pcol = nn & 31;

    const uint32_t aBase = smem_u32(&Asq[0][0]);
    auto cpA = [&](const uint4* wA, int r, int buf) {
        CP_ASYNC16(aBase + ((buf*256 + tid) << 4), wA + (size_t)r*256 + tid);
        CP_COMMIT();
    };

    {
        const float* src0 = (const float*)g_xm + ((size_t)(b*C) << 14)
                          + (size_t)(h0 + prow)*W + (w0 + pcol);
        #pragma unroll
        for (int ks = 0; ks < 8; ks++) {
            const float* src = src0 + ((size_t)(ks*16 + sub*8) << 14);
            float vb[8];
            #pragma unroll
            for (int j = 0; j < 8; j++)
                vb[j] = src[(size_t)j << 14];
            #pragma unroll
            for (int p = 0; p < 4; p++)
                Bsq[ks][(sub*4 + p)*BP + nn] = pk2(vb[2*p], vb[2*p + 1]);
        }
    }

    for (int set = 0; set < 3; set++) {
        const uint4* wA = g_wH1[set];
        const float* bias = (set == 0) ? bq : (set == 1) ? bk : bv_;
        __half* out = (set == 0) ? g_q : (set == 1) ? g_k : g_v;

        float acc[4][4][4];
        #pragma unroll
        for (int i = 0; i < 4; i++)
            #pragma unroll
            for (int j = 0; j < 4; j++)
                #pragma unroll
                for (int r = 0; r < 4; r++) acc[i][j][r] = 0.f;

        cpA(wA, 0, 0);
        CP_WAIT0();
        __syncthreads();

        for (int r = 0; r < 8; r++) {
            int buf = r & 1;
            if (r + 1 < 8) cpA(wA, r + 1, buf ^ 1);
            uint4 af[4];
            #pragma unroll
            for (int i = 0; i < 4; i++)
                af[i] = Asq[buf][(mw*4 + i)*32 + lane];
            uint32_t bf[4][2];
            const int q = lane & 3;
            #pragma unroll
            for (int j = 0; j < 4; j++) {
                int n = nw*32 + j*8 + (lane >> 2);
                bf[j][0] = Bsq[r][ q     *BP + n];
                bf[j][1] = Bsq[r][(4 + q)*BP + n];
            }
            #pragma unroll
            for (int i = 0; i < 4; i++)
                #pragma unroll
                for (int j = 0; j < 4; j++)
                    mma_f16(acc[i][j], (const uint32_t*)&af[i], bf[j]);
            if (r + 1 < 8) {
                CP_WAIT0();
                __syncthreads();
            }
        }

        #pragma unroll
        for (int i = 0; i < 4; i++) {
            int m0 = mw*64 + i*16 + (lane >> 2);
            float bb0 = bias[m0], bb1 = bias[m0 + 8];
            size_t ob = ((size_t)(b*C + m0) << 14) + (size_t)(h0 + nw)*W + w0;
            #pragma unroll
            for (int j = 0; j < 4; j++) {
                int co = j*8 + (lane & 3)*2;
                *(__half2*)(out + ob + co) =
                    __floats2half2_rn(acc[i][j][0] + bb0, acc[i][j][1] + bb0);
                *(__half2*)(out + ob + (8 << 14) + co) =
                    __floats2half2_rn(acc[i][j][2] + bb1, acc[i][j][3] + bb1);
            }
        }
        __syncthreads();
    }
}

// ---------------- local 3x3 attention + blend + residual --------------------
// 8-way channel split (16 ch each), 1 row/CTA, shuffle edge taps.
// q/k/v are fp16 (half traffic).
__global__ void __launch_bounds__(256)
attn_kernel(const float* __restrict__ x, const float* __restrict__ k_b,
            const float* __restrict__ v_b, float* __restrict__ out)
{
    __shared__ float att[8][32][37];

    const int b    = blockIdx.y;
    const int tid  = threadIdx.x;
    const int cg   = tid >> 5;
    const int lane = tid & 31;
    const int h    = blockIdx.x;
    const int wq   = lane*4;
    const size_t bbase = (size_t)b*C*HW;
    const int poff = h*W + wq;
    const int c0 = cg*16;

    float sims[9][4];
    #pragma unroll
    for (int o = 0; o < 9; o++)
        #pragma unroll
        for (int p = 0; p < 4; p++) sims[o][p] = 0.f;

    #pragma unroll 2
    for (int ci = 0; ci < 16; ci++) {
        int c = c0 + ci;
        const __half* kp = g_k + bbase + ((size_t)c << 14);
        float kbv = __ldg(k_b + c);
        uint2 qr = *(const uint2*)(g_q + bbase + ((size_t)c << 14) + poff);
        float q[4] = {h2lo(qr.x), h2hi(qr.x), h2lo(qr.y), h2hi(qr.y)};
        #pragma unroll
        for (int dr = 0; dr < 3; dr++) {
            int hh = h + dr - 1;
            bool rok = ((unsigned)hh < (unsigned)H);
            float m0 = kbv, m1 = kbv, m2 = kbv, m3 = kbv;
            if (rok) {
                uint2 kr = *(const uint2*)(kp + hh*W + wq);
                m0 = h2lo(kr.x); m1 = h2hi(kr.x);
                m2 = h2lo(kr.y); m3 = h2hi(kr.y);
            }
            float lf = __shfl_up_sync(0xffffffffu, m3, 1);
            if (lane == 0)  lf = kbv;
            float rt = __shfl_down_sync(0xffffffffu, m0, 1);
            if (lane == 31) rt = kbv;
            float val[6] = {lf, m0, m1, m2, m3, rt};
            #pragma unroll
            for (int dj = 0; dj < 3; dj++)
                #pragma unroll
                for (int p = 0; p < 4; p++)
                    sims[dr*3 + dj][p] = fmaf(q[p], val[p + dj], sims[dr*3 + dj][p]);
        }
    }

    #pragma unroll
    for (int o = 0; o < 9; o++)
        #pragma unroll
        for (int p = 0; p < 4; p++)
            att[cg][lane][o*4 + p] = sims[o][p];
    __syncthreads();

    #pragma unroll
    for (int o = 0; o < 9; o++) {
        #pragma unroll
        for (int p = 0; p < 4; p++) {
            float s = 0.f;
            #pragma unroll
            for (int gr = 0; gr < 8; gr++)
                s += att[gr][lane][o*4 + p];
            sims[o][p] = s;
        }
    }
    #pragma unroll
    for (int p = 0; p < 4; p++) {
        float mx = sims[0][p];
        #pragma unroll
        for (int o = 1; o < 9; o++) mx = fmaxf(mx, sims[o][p]);
        float se = 0.f;
        #pragma unroll
        for (int o = 0; o < 9; o++) { sims[o][p] = __expf(sims[o][p] - mx); se += sims[o][p]; }
        float inv = 1.f / se;
        #pragma unroll
        for (int o = 0; o < 9; o++) sims[o][p] *= inv;
    }

    #pragma unroll 2
    for (int ci = 0; ci < 16; ci++) {
        int c = c0 + ci;
        const __half* vp = g_v + bbase + ((size_t)c << 14);
        float vbv = __ldg(v_b + c);
        float o2[4] = {0.f, 0.f, 0.f, 0.f};
        #pragma unroll
        for (int dr = 0; dr < 3; dr++) {
            int hh = h + dr - 1;
            bool rok = ((unsigned)hh < (unsigned)H);
            float m0 = vbv, m1 = vbv, m2 = vbv, m3 = vbv;
            if (rok) {
                uint2 vr = *(const uint2*)(vp + hh*W + wq);
                m0 = h2lo(vr.x); m1 = h2hi(vr.x);
                m2 = h2lo(vr.y); m3 = h2hi(vr.y);
            }
            float lf = __shfl_up_sync(0xffffffffu, m3, 1);
            if (lane == 0)  lf = vbv;
            float rt = __shfl_down_sync(0xffffffffu, m0, 1);
            if (lane == 31) rt = vbv;
            float val[6] = {lf, m0, m1, m2, m3, rt};
            #pragma unroll
            for (int dj = 0; dj < 3; dj++)
                #pragma unroll
                for (int p = 0; p < 4; p++)
                    o2[p] = fmaf(sims[dr*3 + dj][p], val[p + dj], o2[p]);
        }
        size_t idx = bbase + ((size_t)c << 14) + poff;
        float4 mv = *(const float4*)(g_m    + idx);
        float4 o1 = *(const float4*)(g_out1 + idx);
        float4 xv = *(const float4*)(x      + idx);
        float4 ov;
        ov.x = xv.x + o1.x*mv.x + (1.f - mv.x)*o2[0];
        ov.y = xv.y + o1.y*mv.y + (1.f - mv.y)*o2[1];
        ov.z = xv.z + o1.z*mv.z + (1.f - mv.z)*o2[2];
        ov.w = xv.w + o1.w*mv.w + (1.f - mv.w)*o2[3];
        *(float4*)(out + idx) = ov;
    }
}

// ---------------- launch ----------------------------------------------------
extern "C" void kernel_launch(void* const* d_in, const int* in_sizes, int n_in,
                              void* d_out, int out_size)
{
    const float* x  = (const float*)d_in[0];
    const float* w1 = (const float*)d_in[1];
    const float* b1 = (const float*)d_in[2];
    const float* w2 = (const float*)d_in[3];
    const float* b2 = (const float*)d_in[4];
    const float* wm = (const float*)d_in[5];
    const float* bm = (const float*)d_in[6];
    const float* wq = (const float*)d_in[7];
    const float* bq = (const float*)d_in[8];
    const float* wk = (const float*)d_in[9];
    const float* bk = (const float*)d_in[10];
    const float* wv = (const float*)d_in[11];
    const float* bv = (const float*)d_in[12];
    float* out = (float*)d_out;

    cudaFuncSetAttribute(conv1_kernel,  cudaFuncAttributeMaxDynamicSharedMemorySize, CONV_SMEM);
    cudaFuncSetAttribute(conv2m_kernel, cudaFuncAttributeMaxDynamicSharedMemorySize, CONV_SMEM);

    pack_weights<<<216, 256>>>(w1, w2, wm, wq, wk, wv);

    dim3 gc(128, BATCH);
    conv1_kernel<<<gc, 256, CONV_SMEM>>>(x, b1);
    stats_kernel<<<BATCH*C, 512>>>();
    conv2m_kernel<<<gc, 256, CONV_SMEM>>>(b2, bm);
    conv_qkv<<<gc, 256>>>(bq, bk, bv);

    dim3 ga(H, BATCH);
    attn_kernel<<<ga, 256>>>(x, bk, bv, out);
}

// round 14
// speedup vs baseline: 1.1389x; 1.0187x over previous
#include <cuda_runtime.h>
#include <cuda_fp16.h>
#include <cstdint>

#define BATCH 8
#define C 128
#define H 128
#define W 128
#define HW (H*W)

// ---------------- scratch (device globals; no allocation allowed) ----------
__device__ float  g_y1  [BATCH*C*HW];   // conv1 raw output
__device__ float  g_out1[BATCH*C*HW];
__device__ float  g_m   [BATCH*C*HW];
__device__ float  g_xm  [BATCH*C*HW];   // t * m
__device__ __half g_q   [BATCH*C*HW];
__device__ __half g_k   [BATCH*C*HW];
__device__ __half g_v   [BATCH*C*HW];
__device__ float  g_mu  [BATCH*C];
__device__ float  g_rsig[BATCH*C];
// fp16 weights packed in per-thread m16n8k16 fragment order
// (+1 step of slack so the mainloop A-prefetch may harmlessly overread)
__device__ uint4 g_wH3[3][73*8*32];    // 3x3 convs: [(ks*8+fr)*32+lane]
__device__ uint4 g_wH1[3][8*8*32];     // 1x1 convs

__constant__ int c_di[9] = {-1,-1,-1, 0,0,0, 1,1,1};
__constant__ int c_dj[9] = {-1, 0, 1,-1,0,1,-1,0,1};

__device__ __forceinline__ void mma_f16(float* d, const uint32_t* a, const uint32_t* b) {
    asm volatile(
        "mma.sync.aligned.m16n8k16.row.col.f32.f16.f16.f32 "
        "{%0,%1,%2,%3}, {%4,%5,%6,%7}, {%8,%9}, {%0,%1,%2,%3};"
        : "+f"(d[0]), "+f"(d[1]), "+f"(d[2]), "+f"(d[3])
        : "r"(a[0]), "r"(a[1]), "r"(a[2]), "r"(a[3]), "r"(b[0]), "r"(b[1]));
}
__device__ __forceinline__ uint32_t smem_u32(const void* p) {
    uint32_t a;
    asm("{ .reg .u64 t; cvta.to.shared.u64 t, %1; cvt.u32.u64 %0, t; }"
        : "=r"(a) : "l"(p));
    return a;
}
__device__ __forceinline__ uint32_t pk2(float lo, float hi) {
    __half2 h = __floats2half2_rn(lo, hi);
    return *(uint32_t*)&h;
}
__device__ __forceinline__ float h2lo(uint32_t w) {
    return __low2float(*(__half2*)&w);
}
__device__ __forceinline__ float h2hi(uint32_t w) {
    return __high2float(*(__half2*)&w);
}
#define CP_ASYNC16(dst, src) \
    asm volatile("cp.async.ca.shared.global [%0], [%1], 16;" :: "r"(dst), "l"(src))
#define CP_COMMIT() asm volatile("cp.async.commit_group;")
#define CP_WAIT0()  asm volatile("cp.async.wait_group 0;" ::: "memory")

// ---------------- weight packing (fp16 fragment order) ----------------------
__global__ void pack_weights(const float* __restrict__ w1, const float* __restrict__ w2,
                             const float* __restrict__ wm, const float* __restrict__ wq,
                             const float* __restrict__ wk, const float* __restrict__ wv)
{
    int idx = blockIdx.x * blockDim.x + threadIdx.x;
    int lane = idx & 31;
    int fr   = (idx >> 5) & 7;
    int rest = idx >> 8;
    {
        int ks   = rest % 72;
        int conv = rest / 72;
        if (conv < 3) {
            const float* w = (conv == 0) ? w1 : (conv == 1) ? w2 : wm;
            int m0  = fr*16 + (lane >> 2);
            int kq  = lane & 3;
            int tap = ks >> 3;
            int cb  = (ks & 7) << 4;
            int ca  = cb + 2*kq;
            int cc  = cb + 8 + 2*kq;
            uint4 o;
            o.x = pk2(w[ m0   *1152 + ca*9 + tap], w[ m0   *1152 + (ca+1)*9 + tap]);
            o.y = pk2(w[(m0+8)*1152 + ca*9 + tap], w[(m0+8)*1152 + (ca+1)*9 + tap]);
            o.z = pk2(w[ m0   *1152 + cc*9 + tap], w[ m0   *1152 + (cc+1)*9 + tap]);
            o.w = pk2(w[(m0+8)*1152 + cc*9 + tap], w[(m0+8)*1152 + (cc+1)*9 + tap]);
            g_wH3[conv][(ks*8 + fr)*32 + lane] = o;
        }
    }
    if (idx < 3*8*8*32) {
        int ks  = rest % 8;
        int set = rest / 8;
        const float* w = (set == 0) ? wq : (set == 1) ? wk : wv;
        int m0 = fr*16 + (lane >> 2);
        int kq = lane & 3;
        int cb = ks << 4;
        int ca = cb + 2*kq;
        int cc = cb + 8 + 2*kq;
        uint4 o;
        o.x = pk2(w[ m0   *128 + ca], w[ m0   *128 + ca+1]);
        o.y = pk2(w[(m0+8)*128 + ca], w[(m0+8)*128 + ca+1]);
        o.z = pk2(w[ m0   *128 + cc], w[ m0   *128 + cc+1]);
        o.w = pk2(w[(m0+8)*128 + cc], w[(m0+8)*128 + cc+1]);
        g_wH1[set][(ks*8 + fr)*32 + lane] = o;
    }
}

// ---------------- stats only (mu, rsig per (b,c)) ----------------------------
__global__ void __launch_bounds__(512)
stats_kernel()
{
    int bc = blockIdx.x;
    const float4* p = (const float4*)(g_y1 + (size_t)bc * HW);
    float s = 0.f, sq = 0.f;
    #pragma unroll
    for (int i = 0; i < 8; i++) {
        float4 v = p[threadIdx.x + 512*i];
        s  += (v.x + v.y) + (v.z + v.w);
        sq += v.x*v.x + v.y*v.y + v.z*v.z + v.w*v.w;
    }
    #pragma unroll
    for (int o = 16; o; o >>= 1) {
        s  += __shfl_xor_sync(0xffffffffu, s,  o);
        sq += __shfl_xor_sync(0xffffffffu, sq, o);
    }
    __shared__ float ss[16], sqq[16];
    int wrp = threadIdx.x >> 5;
    if ((threadIdx.x & 31) == 0) { ss[wrp] = s; sqq[wrp] = sq; }
    __syncthreads();
    if (threadIdx.x == 0) {
        float S = 0.f, Q = 0.f;
        #pragma unroll
        for (int i = 0; i < 16; i++) { S += ss[i]; Q += sqq[i]; }
        float mu  = S / (float)HW;
        float var = Q / (float)HW - mu*mu;
        g_mu[bc]   = mu;
        g_rsig[bc] = rsqrtf(var + 1e-5f);
    }
}

// ---------------- fp16 3x3 conv core (B-stationary tile) ---------------------
// Restructured: tap-outer loop (B base pointer computed once per tap),
// unrolled 8-step inner loop (immediate-offset LDS, pointer-bump A prefetch).
#define TPIX 204
#define TSTRIDE 68
#define CONV_SMEM (TPIX*TSTRIDE*4)     // 55488 B

__device__ __forceinline__ void conv_pass(const uint32_t* tile, const uint4* wA,
                                          int mw, int nw, int lane,
                                          float acc[4][4][4])
{
    const int q = lane & 3, g = lane >> 2;
    uint4 aN[4];
    #pragma unroll
    for (int i = 0; i < 4; i++)
        aN[i] = wA[(mw*4 + i)*32 + lane];
    const uint4* aSrc = wA + 256 + (mw*4)*32 + lane;

    for (int tap = 0; tap < 9; tap++) {
        const uint32_t* bp = tile
            + ((nw + c_di[tap] + 1)*34 + c_dj[tap] + 1 + g)*TSTRIDE + q;
        #pragma unroll
        for (int k8 = 0; k8 < 8; k8++) {
            uint4 aC[4];
            #pragma unroll
            for (int i = 0; i < 4; i++) aC[i] = aN[i];
            #pragma unroll
            for (int i = 0; i < 4; i++)
                aN[i] = aSrc[i*32];
            aSrc += 256;
            uint32_t bf[4][2];
            #pragma unroll
            for (int j = 0; j < 4; j++) {
                bf[j][0] = bp[j*8*TSTRIDE + k8*8];
                bf[j][1] = bp[j*8*TSTRIDE + k8*8 + 4];
            }
            #pragma unroll
            for (int i = 0; i < 4; i++)
                #pragma unroll
                for (int j = 0; j < 4; j++)
                    mma_f16(acc[i][j], (const uint32_t*)&aC[i], bf[j]);
        }
    }
}

// ---------------- conv1: raw x -> y1 -----------------------------------------
__global__ void __launch_bounds__(256, 2)
conv1_kernel(const float* __restrict__ in, const float* __restrict__ bias)
{
    extern __shared__ uint32_t tile[];

    const int tid  = threadIdx.x;
    const int lane = tid & 31, wid = tid >> 5;
    const int mw = wid >> 2, nw = wid & 3;
    const int b  = blockIdx.y;
    const int h0 = (blockIdx.x >> 2) << 2;
    const int w0 = (blockIdx.x & 3) << 5;

    #pragma unroll 4
    for (int pp = 0; pp < 51; pp++) {
        int idx  = pp*256 + tid;
        int pair = idx / 204;
        int pix  = idx - pair*204;
        int pr = pix / 34, pc = pix - pr*34;
        int ih = h0 + pr - 1, iw = w0 + pc - 1;
        float v0 = 0.f, v1 = 0.f;
        if (((unsigned)ih < (unsigned)H) && ((unsigned)iw < (unsigned)W)) {
            const float* s = in + ((size_t)(b*C + 2*pair) << 14) + (size_t)ih*W + iw;
            v0 = s[0];
            v1 = s[(size_t)1 << 14];
        }
        tile[pix*TSTRIDE + pair] = pk2(v0, v1);
    }
    __syncthreads();

    float acc[4][4][4];
    #pragma unroll
    for (int i = 0; i < 4; i++)
        #pragma unroll
        for (int j = 0; j < 4; j++)
            #pragma unroll
            for (int r = 0; r < 4; r++) acc[i][j][r] = 0.f;

    conv_pass(tile, g_wH3[0], mw, nw, lane, acc);

    const int q = lane & 3, g = lane >> 2;
    #pragma unroll
    for (int i = 0; i < 4; i++) {
        int m0 = mw*64 + i*16 + g;
        float bb0 = bias[m0], bb1 = bias[m0 + 8];
        size_t ob = ((size_t)(b*C + m0) << 14) + (size_t)(h0 + nw)*W + w0;
        #pragma unroll
        for (int j = 0; j < 4; j++) {
            int co = j*8 + q*2;
            *(float2*)(g_y1 + ob + co) =
                make_float2(acc[i][j][0] + bb0, acc[i][j][1] + bb0);
            *(float2*)(g_y1 + ob + (8 << 14) + co) =
                make_float2(acc[i][j][2] + bb1, acc[i][j][3] + bb1);
        }
    }
}

// ---------------- merged conv2 + mask: one staged t-tile, two passes ---------
__global__ void __launch_bounds__(256, 2)
conv2m_kernel(const float* __restrict__ b2, const float* __restrict__ bm)
{
    extern __shared__ uint32_t tile[];

    const int tid  = threadIdx.x;
    const int lane = tid & 31, wid = tid >> 5;
    const int mw = wid >> 2, nw = wid & 3;
    const int b  = blockIdx.y;
    const int h0 = (blockIdx.x >> 2) << 2;
    const int w0 = (blockIdx.x & 3) << 5;
    const int q = lane & 3, g = lane >> 2;

    const float* mup = g_mu   + b*C;
    const float* rsp = g_rsig + b*C;

    // stage t = leaky(norm(y1)) as fp16
    #pragma unroll 4
    for (int pp = 0; pp < 51; pp++) {
        int idx  = pp*256 + tid;
        int pair = idx / 204;
        int pix  = idx - pair*204;
        int pr = pix / 34, pc = pix - pr*34;
        int ih = h0 + pr - 1, iw = w0 + pc - 1;
        float v0 = 0.f, v1 = 0.f;
        if (((unsigned)ih < (unsigned)H) && ((unsigned)iw < (unsigned)W)) {
            const float* s = g_y1 + ((size_t)(b*C + 2*pair) << 14) + (size_t)ih*W + iw;
            float y0 = s[0], y1v = s[(size_t)1 << 14];
            float t0 = (y0  - mup[2*pair])   * rsp[2*pair];
            float t1 = (y1v - mup[2*pair+1]) * rsp[2*pair+1];
            v0 = (t0 < 0.f) ? 0.2f*t0 : t0;
            v1 = (t1 < 0.f) ? 0.2f*t1 : t1;
        }
        tile[pix*TSTRIDE + pair] = pk2(v0, v1);
    }
    __syncthreads();

    float acc[4][4][4];

    // ---- pass 1: conv2 -> out1 ----
    #pragma unroll
    for (int i = 0; i < 4; i++)
        #pragma unroll
        for (int j = 0; j < 4; j++)
            #pragma unroll
            for (int r = 0; r < 4; r++) acc[i][j][r] = 0.f;
    conv_pass(tile, g_wH3[1], mw, nw, lane, acc);
    #pragma unroll
    for (int i = 0; i < 4; i++) {
        int m0 = mw*64 + i*16 + g;
        float bb0 = b2[m0], bb1 = b2[m0 + 8];
        size_t ob = ((size_t)(b*C + m0) << 14) + (size_t)(h0 + nw)*W + w0;
        #pragma unroll
        for (int j = 0; j < 4; j++) {
            int co = j*8 + q*2;
            *(float2*)(g_out1 + ob + co) =
                make_float2(acc[i][j][0] + bb0, acc[i][j][1] + bb0);
            *(float2*)(g_out1 + ob + (8 << 14) + co) =
                make_float2(acc[i][j][2] + bb1, acc[i][j][3] + bb1);
        }
    }

    // ---- pass 2: mask -> m, xm = t*m (t from staged fp16 tile) ----
    #pragma unroll
    for (int i = 0; i < 4; i++)
        #pragma unroll
        for (int j = 0; j < 4; j++)
            #pragma unroll
            for (int r = 0; r < 4; r++) acc[i][j][r] = 0.f;
    conv_pass(tile, g_wH3[2], mw, nw, lane, acc);
    #pragma unroll
    for (int i = 0; i < 4; i++) {
        int m0 = mw*64 + i*16 + g;
        int mh = m0 >> 1;
        int par = m0 & 1;
        float bb0 = bm[m0], bb1 = bm[m0 + 8];
        size_t ob = ((size_t)(b*C + m0) << 14) + (size_t)(h0 + nw)*W + w0;
        #pragma unroll
        for (int j = 0; j < 4; j++) {
            int co = j*8 + q*2;
            int pix = (nw + 1)*34 + co + 1;
            uint32_t wa0 = tile[ pix     *TSTRIDE + mh];
            uint32_t wa1 = tile[(pix + 1)*TSTRIDE + mh];
            uint32_t wb0 = tile[ pix     *TSTRIDE + mh + 4];
            uint32_t wb1 = tile[(pix + 1)*TSTRIDE + mh + 4];
            float t00 = par ? h2hi(wa0) : h2lo(wa0);
            float t01 = par ? h2hi(wa1) : h2lo(wa1);
            float t10 = par ? h2hi(wb0) : h2lo(wb0);
            float t11 = par ? h2hi(wb1) : h2lo(wb1);
            float s0 = 1.f/(1.f + __expf(-(acc[i][j][0] + bb0)));
            float s1 = 1.f/(1.f + __expf(-(acc[i][j][1] + bb0)));
            float s2 = 1.f/(1.f + __expf(-(acc[i][j][2] + bb1)));
            float s3 = 1.f/(1.f + __expf(-(acc[i][j][3] + bb1)));
            *(float2*)(g_m + ob + co)             = make_float2(s0, s1);
            *(float2*)(g_m + ob + (8 << 14) + co) = make_float2(s2, s3);
            *(float2*)(g_xm + ob + co)             = make_float2(s0*t00, s1*t01);
            *(float2*)(g_xm + ob + (8 << 14) + co) = make_float2(s2*t10, s3*t11);
        }
    }
}

// ---------------- merged q/k/v 1x1 GEMM (fp16 outputs) -----------------------
#define BP 136
__global__ void __launch_bounds__(256, 2)
conv_qkv(const float* __restrict__ bq, const float* __restrict__ bk,
         const float* __restrict__ bv_)
{
    __shared__ uint32_t Bsq[8][8*BP];
    __shared__ uint4    Asq[2][256];

    const int tid  = threadIdx.x;
    const int lane = tid & 31, wid = tid >> 5;
    const int mw = wid >> 2, nw = wid & 3;
    const int b  = blockIdx.y;
    const int h0 = (blockIdx.x >> 2) << 2;
    const int w0 = (blockIdx.x & 3) << 5;

    const int sub  = tid >> 7;
    const int nn   = tid & 127;
    const int prow = nn >> 5, pcol = nn & 31;

    const uint32_t aBase = smem_u32(&Asq[0][0]);
    auto cpA = [&](const uint4* wA, int r, int buf) {
        CP_ASYNC16(aBase + ((buf*256 + tid) << 4), wA + (size_t)r*256 + tid);
        CP_COMMIT();
    };

    {
        const float* src0 = (const float*)g_xm + ((size_t)(b*C) << 14)
                          + (size_t)(h0 + prow)*W + (w0 + pcol);
        #pragma unroll
        for (int ks = 0; ks < 8; ks++) {
            const float* src = src0 + ((size_t)(ks*16 + sub*8) << 14);
            float vb[8];
            #pragma unroll
            for (int j = 0; j < 8; j++)
                vb[j] = src[(size_t)j << 14];
            #pragma unroll
            for (int p = 0; p < 4; p++)
                Bsq[ks][(sub*4 + p)*BP + nn] = pk2(vb[2*p], vb[2*p + 1]);
        }
    }

    for (int set = 0; set < 3; set++) {
        const uint4* wA = g_wH1[set];
        const float* bias = (set == 0) ? bq : (set == 1) ? bk : bv_;
        __half* out = (set == 0) ? g_q : (set == 1) ? g_k : g_v;

        float acc[4][4][4];
        #pragma unroll
        for (int i = 0; i < 4; i++)
            #pragma unroll
            for (int j = 0; j < 4; j++)
                #pragma unroll
                for (int r = 0; r < 4; r++) acc[i][j][r] = 0.f;

        cpA(wA, 0, 0);
        CP_WAIT0();
        __syncthreads();

        for (int r = 0; r < 8; r++) {
            int buf = r & 1;
            if (r + 1 < 8) cpA(wA, r + 1, buf ^ 1);
            uint4 af[4];
            #pragma unroll
            for (int i = 0; i < 4; i++)
                af[i] = Asq[buf][(mw*4 + i)*32 + lane];
            uint32_t bf[4][2];
            const int q = lane & 3;
            #pragma unroll
            for (int j = 0; j < 4; j++) {
                int n = nw*32 + j*8 + (lane >> 2);
                bf[j][0] = Bsq[r][ q     *BP + n];
                bf[j][1] = Bsq[r][(4 + q)*BP + n];
            }
            #pragma unroll
            for (int i = 0; i < 4; i++)
                #pragma unroll
                for (int j = 0; j < 4; j++)
                    mma_f16(acc[i][j], (const uint32_t*)&af[i], bf[j]);
            if (r + 1 < 8) {
                CP_WAIT0();
                __syncthreads();
            }
        }

        #pragma unroll
        for (int i = 0; i < 4; i++) {
            int m0 = mw*64 + i*16 + (lane >> 2);
            float bb0 = bias[m0], bb1 = bias[m0 + 8];
            size_t ob = ((size_t)(b*C + m0) << 14) + (size_t)(h0 + nw)*W + w0;
            #pragma unroll
            for (int j = 0; j < 4; j++) {
                int co = j*8 + (lane & 3)*2;
                *(__half2*)(out + ob + co) =
                    __floats2half2_rn(acc[i][j][0] + bb0, acc[i][j][1] + bb0);
                *(__half2*)(out + ob + (8 << 14) + co) =
                    __floats2half2_rn(acc[i][j][2] + bb1, acc[i][j][3] + bb1);
            }
        }
        __syncthreads();
    }
}

// ---------------- local 3x3 attention + blend + residual --------------------
// 8-way channel split (16 ch each), 1 row/CTA, shuffle edge taps, fp16 qkv.
__global__ void __launch_bounds__(256)
attn_kernel(const float* __restrict__ x, const float* __restrict__ k_b,
            const float* __restrict__ v_b, float* __restrict__ out)
{
    __shared__ float att[8][32][37];

    const int b    = blockIdx.y;
    const int tid  = threadIdx.x;
    const int cg   = tid >> 5;
    const int lane = tid & 31;
    const int h    = blockIdx.x;
    const int wq   = lane*4;
    const size_t bbase = (size_t)b*C*HW;
    const int poff = h*W + wq;
    const int c0 = cg*16;

    float sims[9][4];
    #pragma unroll
    for (int o = 0; o < 9; o++)
        #pragma unroll
        for (int p = 0; p < 4; p++) sims[o][p] = 0.f;

    #pragma unroll 2
    for (int ci = 0; ci < 16; ci++) {
        int c = c0 + ci;
        const __half* kp = g_k + bbase + ((size_t)c << 14);
        float kbv = __ldg(k_b + c);
        uint2 qr = *(const uint2*)(g_q + bbase + ((size_t)c << 14) + poff);
        float q[4] = {h2lo(qr.x), h2hi(qr.x), h2lo(qr.y), h2hi(qr.y)};
        #pragma unroll
        for (int dr = 0; dr < 3; dr++) {
            int hh = h + dr - 1;
            bool rok = ((unsigned)hh < (unsigned)H);
            float m0 = kbv, m1 = kbv, m2 = kbv, m3 = kbv;
            if (rok) {
                uint2 kr = *(const uint2*)(kp + hh*W + wq);
                m0 = h2lo(kr.x); m1 = h2hi(kr.x);
                m2 = h2lo(kr.y); m3 = h2hi(kr.y);
            }
            float lf = __shfl_up_sync(0xffffffffu, m3, 1);
            if (lane == 0)  lf = kbv;
            float rt = __shfl_down_sync(0xffffffffu, m0, 1);
            if (lane == 31) rt = kbv;
            float val[6] = {lf, m0, m1, m2, m3, rt};
            #pragma unroll
            for (int dj = 0; dj < 3; dj++)
                #pragma unroll
                for (int p = 0; p < 4; p++)
                    sims[dr*3 + dj][p] = fmaf(q[p], val[p + dj], sims[dr*3 + dj][p]);
        }
    }

    #pragma unroll
    for (int o = 0; o < 9; o++)
        #pragma unroll
        for (int p = 0; p < 4; p++)
            att[cg][lane][o*4 + p] = sims[o][p];
    __syncthreads();

    #pragma unroll
    for (int o = 0; o < 9; o++) {
        #pragma unroll
        for (int p = 0; p < 4; p++) {
            float s = 0.f;
            #pragma unroll
            for (int gr = 0; gr < 8; gr++)
                s += att[gr][lane][o*4 + p];
            sims[o][p] = s;
        }
    }
    #pragma unroll
    for (int p = 0; p < 4; p++) {
        float mx = sims[0][p];
        #pragma unroll
        for (int o = 1; o < 9; o++) mx = fmaxf(mx, sims[o][p]);
        float se = 0.f;
        #pragma unroll
        for (int o = 0; o < 9; o++) { sims[o][p] = __expf(sims[o][p] - mx); se += sims[o][p]; }
        float inv = 1.f / se;
        #pragma unroll
        for (int o = 0; o < 9; o++) sims[o][p] *= inv;
    }

    #pragma unroll 2
    for (int ci = 0; ci < 16; ci++) {
        int c = c0 + ci;
        const __half* vp = g_v + bbase + ((size_t)c << 14);
        float vbv = __ldg(v_b + c);
        float o2[4] = {0.f, 0.f, 0.f, 0.f};
        #pragma unroll
        for (int dr = 0; dr < 3; dr++) {
            int hh = h + dr - 1;
            bool rok = ((unsigned)hh < (unsigned)H);
            float m0 = vbv, m1 = vbv, m2 = vbv, m3 = vbv;
            if (rok) {
                uint2 vr = *(const uint2*)(vp + hh*W + wq);
                m0 = h2lo(vr.x); m1 = h2hi(vr.x);
                m2 = h2lo(vr.y); m3 = h2hi(vr.y);
            }
            float lf = __shfl_up_sync(0xffffffffu, m3, 1);
            if (lane == 0)  lf = vbv;
            float rt = __shfl_down_sync(0xffffffffu, m0, 1);
            if (lane == 31) rt = vbv;
            float val[6] = {lf, m0, m1, m2, m3, rt};
            #pragma unroll
            for (int dj = 0; dj < 3; dj++)
                #pragma unroll
                for (int p = 0; p < 4; p++)
                    o2[p] = fmaf(sims[dr*3 + dj][p], val[p + dj], o2[p]);
        }
        size_t idx = bbase + ((size_t)c << 14) + poff;
        float4 mv = *(const float4*)(g_m    + idx);
        float4 o1 = *(const float4*)(g_out1 + idx);
        float4 xv = *(const float4*)(x      + idx);
        float4 ov;
        ov.x = xv.x + o1.x*mv.x + (1.f - mv.x)*o2[0];
        ov.y = xv.y + o1.y*mv.y + (1.f - mv.y)*o2[1];
        ov.z = xv.z + o1.z*mv.z + (1.f - mv.z)*o2[2];
        ov.w = xv.w + o1.w*mv.w + (1.f - mv.w)*o2[3];
        *(float4*)(out + idx) = ov;
    }
}

// ---------------- launch ----------------------------------------------------
extern "C" void kernel_launch(void* const* d_in, const int* in_sizes, int n_in,
                              void* d_out, int out_size)
{
    const float* x  = (const float*)d_in[0];
    const float* w1 = (const float*)d_in[1];
    const float* b1 = (const float*)d_in[2];
    const float* w2 = (const float*)d_in[3];
    const float* b2 = (const float*)d_in[4];
    const float* wm = (const float*)d_in[5];
    const float* bm = (const float*)d_in[6];
    const float* wq = (const float*)d_in[7];
    const float* bq = (const float*)d_in[8];
    const float* wk = (const float*)d_in[9];
    const float* bk = (const float*)d_in[10];
    const float* wv = (const float*)d_in[11];
    const float* bv = (const float*)d_in[12];
    float* out = (float*)d_out;

    cudaFuncSetAttribute(conv1_kernel,  cudaFuncAttributeMaxDynamicSharedMemorySize, CONV_SMEM);
    cudaFuncSetAttribute(conv2m_kernel, cudaFuncAttributeMaxDynamicSharedMemorySize, CONV_SMEM);

    pack_weights<<<216, 256>>>(w1, w2, wm, wq, wk, wv);

    dim3 gc(128, BATCH);
    conv1_kernel<<<gc, 256, CONV_SMEM>>>(x, b1);
    stats_kernel<<<BATCH*C, 512>>>();
    conv2m_kernel<<<gc, 256, CONV_SMEM>>>(b2, bm);
    conv_qkv<<<gc, 256>>>(bq, bk, bv);

    dim3 ga(H, BATCH);
    attn_kernel<<<ga, 256>>>(x, bk, bv, out);
}

// round 15
// speedup vs baseline: 1.1471x; 1.0072x over previous
#include <cuda_runtime.h>
#include <cuda_fp16.h>
#include <cstdint>

#define BATCH 8
#define C 128
#define H 128
#define W 128
#define HW (H*W)

// ---------------- scratch (device globals; no allocation allowed) ----------
__device__ float  g_y1  [BATCH*C*HW];   // conv1 raw output
__device__ __half g_out1[BATCH*C*HW];
__device__ __half g_m   [BATCH*C*HW];
__device__ __half g_xm  [BATCH*C*HW];   // t * m
__device__ __half g_q   [BATCH*C*HW];
__device__ __half g_k   [BATCH*C*HW];
__device__ __half g_v   [BATCH*C*HW];
__device__ float  g_mu  [BATCH*C];
__device__ float  g_rsig[BATCH*C];
// fp16 weights packed in per-thread m16n8k16 fragment order
__device__ uint4 g_wH3[3][72*8*32];    // 3x3 convs: [(ks*8+fr)*32+lane]
__device__ uint4 g_wH1[3][8*8*32];     // 1x1 convs

__constant__ int c_di[9] = {-1,-1,-1, 0,0,0, 1,1,1};
__constant__ int c_dj[9] = {-1, 0, 1,-1,0,1,-1,0,1};

__device__ __forceinline__ void mma_f16(float* d, const uint32_t* a, const uint32_t* b) {
    asm volatile(
        "mma.sync.aligned.m16n8k16.row.col.f32.f16.f16.f32 "
        "{%0,%1,%2,%3}, {%4,%5,%6,%7}, {%8,%9}, {%0,%1,%2,%3};"
        : "+f"(d[0]), "+f"(d[1]), "+f"(d[2]), "+f"(d[3])
        : "r"(a[0]), "r"(a[1]), "r"(a[2]), "r"(a[3]), "r"(b[0]), "r"(b[1]));
}
__device__ __forceinline__ uint32_t smem_u32(const void* p) {
    uint32_t a;
    asm("{ .reg .u64 t; cvta.to.shared.u64 t, %1; cvt.u32.u64 %0, t; }"
        : "=r"(a) : "l"(p));
    return a;
}
__device__ __forceinline__ uint32_t pk2(float lo, float hi) {
    __half2 h = __floats2half2_rn(lo, hi);
    return *(uint32_t*)&h;
}
__device__ __forceinline__ uint32_t pkh(__half lo, __half hi) {
    __half2 h = __halves2half2(lo, hi);
    return *(uint32_t*)&h;
}
__device__ __forceinline__ float h2lo(uint32_t w) {
    return __low2float(*(__half2*)&w);
}
__device__ __forceinline__ float h2hi(uint32_t w) {
    return __high2float(*(__half2*)&w);
}
#define CP_ASYNC16(dst, src) \
    asm volatile("cp.async.ca.shared.global [%0], [%1], 16;" :: "r"(dst), "l"(src))
#define CP_COMMIT() asm volatile("cp.async.commit_group;")
#define CP_WAIT0()  asm volatile("cp.async.wait_group 0;" ::: "memory")
#define CP_WAIT1()  asm volatile("cp.async.wait_group 1;" ::: "memory")

// ---------------- weight packing (fp16 fragment order) ----------------------
__global__ void pack_weights(const float* __restrict__ w1, const float* __restrict__ w2,
                             const float* __restrict__ wm, const float* __restrict__ wq,
                             const float* __restrict__ wk, const float* __restrict__ wv)
{
    int idx = blockIdx.x * blockDim.x + threadIdx.x;
    int lane = idx & 31;
    int fr   = (idx >> 5) & 7;
    int rest = idx >> 8;
    {
        int ks   = rest % 72;
        int conv = rest / 72;
        if (conv < 3) {
            const float* w = (conv == 0) ? w1 : (conv == 1) ? w2 : wm;
            int m0  = fr*16 + (lane >> 2);
            int kq  = lane & 3;
            int tap = ks >> 3;
            int cb  = (ks & 7) << 4;
            int ca  = cb + 2*kq;
            int cc  = cb + 8 + 2*kq;
            uint4 o;
            o.x = pk2(w[ m0   *1152 + ca*9 + tap], w[ m0   *1152 + (ca+1)*9 + tap]);
            o.y = pk2(w[(m0+8)*1152 + ca*9 + tap], w[(m0+8)*1152 + (ca+1)*9 + tap]);
            o.z = pk2(w[ m0   *1152 + cc*9 + tap], w[ m0   *1152 + (cc+1)*9 + tap]);
            o.w = pk2(w[(m0+8)*1152 + cc*9 + tap], w[(m0+8)*1152 + (cc+1)*9 + tap]);
            g_wH3[conv][(ks*8 + fr)*32 + lane] = o;
        }
    }
    if (idx < 3*8*8*32) {
        int ks  = rest % 8;
        int set = rest / 8;
        const float* w = (set == 0) ? wq : (set == 1) ? wk : wv;
        int m0 = fr*16 + (lane >> 2);
        int kq = lane & 3;
        int cb = ks << 4;
        int ca = cb + 2*kq;
        int cc = cb + 8 + 2*kq;
        uint4 o;
        o.x = pk2(w[ m0   *128 + ca], w[ m0   *128 + ca+1]);
        o.y = pk2(w[(m0+8)*128 + ca], w[(m0+8)*128 + ca+1]);
        o.z = pk2(w[ m0   *128 + cc], w[ m0   *128 + cc+1]);
        o.w = pk2(w[(m0+8)*128 + cc], w[(m0+8)*128 + cc+1]);
        g_wH1[set][(ks*8 + fr)*32 + lane] = o;
    }
}

// ---------------- stats only (mu, rsig per (b,c)) ----------------------------
__global__ void __launch_bounds__(512)
stats_kernel()
{
    int bc = blockIdx.x;
    const float4* p = (const float4*)(g_y1 + (size_t)bc * HW);
    float s = 0.f, sq = 0.f;
    #pragma unroll
    for (int i = 0; i < 8; i++) {
        float4 v = p[threadIdx.x + 512*i];
        s  += (v.x + v.y) + (v.z + v.w);
        sq += v.x*v.x + v.y*v.y + v.z*v.z + v.w*v.w;
    }
    #pragma unroll
    for (int o = 16; o; o >>= 1) {
        s  += __shfl_xor_sync(0xffffffffu, s,  o);
        sq += __shfl_xor_sync(0xffffffffu, sq, o);
    }
    __shared__ float ss[16], sqq[16];
    int wrp = threadIdx.x >> 5;
    if ((threadIdx.x & 31) == 0) { ss[wrp] = s; sqq[wrp] = sq; }
    __syncthreads();
    if (threadIdx.x == 0) {
        float S = 0.f, Q = 0.f;
        #pragma unroll
        for (int i = 0; i < 16; i++) { S += ss[i]; Q += sqq[i]; }
        float mu  = S / (float)HW;
        float var = Q / (float)HW - mu*mu;
        g_mu[bc]   = mu;
        g_rsig[bc] = rsqrtf(var + 1e-5f);
    }
}

// ---------------- fp16 3x3 conv core (B-stationary tile, A cp.async ring) ---
#define TPIX 204
#define TSTRIDE 68
#define TILE_WORDS (TPIX*TSTRIDE)            // 13872
#define A_HT 1024                            // uint4 per half-tap (4 steps)
#define CONV_SMEM (TILE_WORDS*4 + 2*A_HT*16) // 55488 + 32768 = 88256 B

__device__ __forceinline__ void conv_pass(const uint32_t* tile, uint4* Ab,
                                          const uint4* wA, int mw, int nw,
                                          int lane, float acc[4][4][4])
{
    const int q = lane & 3, g = lane >> 2;
    const int tid = threadIdx.x;
    const uint32_t aBase = smem_u32(Ab);

    auto issue = [&](int hs, int buf) {
        const uint4* src = wA + hs*A_HT + tid;
        uint32_t d = aBase + ((buf*A_HT + tid) << 4);
        CP_ASYNC16(d,              src);
        CP_ASYNC16(d + (256 << 4), src + 256);
        CP_ASYNC16(d + (512 << 4), src + 512);
        CP_ASYNC16(d + (768 << 4), src + 768);
        CP_COMMIT();
    };

    issue(0, 0);
    for (int hs = 0; hs < 18; hs++) {
        int cur = hs & 1;
        __syncthreads();                       // prior readers of buf cur^1 done
        if (hs + 1 < 18) { issue(hs + 1, cur ^ 1); CP_WAIT1(); }
        else             { CP_WAIT0(); }
        __syncthreads();                       // group hs visible to all

        int tap = hs >> 1;
        const uint32_t* bp = tile
            + ((nw + c_di[tap] + 1)*34 + c_dj[tap] + 1 + g)*TSTRIDE
            + q + (hs & 1)*32;
        const uint4* ap = Ab + cur*A_HT + (mw*4)*32 + lane;
        #pragma unroll
        for (int s = 0; s < 4; s++) {
            uint4 aC[4];
            #pragma unroll
            for (int i = 0; i < 4; i++)
                aC[i] = ap[(s*8 + i)*32];
            uint32_t bf[4][2];
            #pragma unroll
            for (int j = 0; j < 4; j++) {
                bf[j][0] = bp[j*8*TSTRIDE + s*8];
                bf[j][1] = bp[j*8*TSTRIDE + s*8 + 4];
            }
            #pragma unroll
            for (int i = 0; i < 4; i++)
                #pragma unroll
                for (int j = 0; j < 4; j++)
                    mma_f16(acc[i][j], (const uint32_t*)&aC[i], bf[j]);
        }
    }
}

// ---------------- conv1: raw x -> y1 -----------------------------------------
__global__ void __launch_bounds__(256, 2)
conv1_kernel(const float* __restrict__ in, const float* __restrict__ bias)
{
    extern __shared__ uint32_t tile[];
    uint4* Ab = (uint4*)(tile + TILE_WORDS);

    const int tid  = threadIdx.x;
    const int lane = tid & 31, wid = tid >> 5;
    const int mw = wid >> 2, nw = wid & 3;
    const int b  = blockIdx.y;
    const int h0 = (blockIdx.x >> 2) << 2;
    const int w0 = (blockIdx.x & 3) << 5;

    #pragma unroll 4
    for (int pp = 0; pp < 51; pp++) {
        int idx  = pp*256 + tid;
        int pair = idx / 204;
        int pix  = idx - pair*204;
        int pr = pix / 34, pc = pix - pr*34;
        int ih = h0 + pr - 1, iw = w0 + pc - 1;
        float v0 = 0.f, v1 = 0.f;
        if (((unsigned)ih < (unsigned)H) && ((unsigned)iw < (unsigned)W)) {
            const float* s = in + ((size_t)(b*C + 2*pair) << 14) + (size_t)ih*W + iw;
            v0 = s[0];
            v1 = s[(size_t)1 << 14];
        }
        tile[pix*TSTRIDE + pair] = pk2(v0, v1);
    }
    __syncthreads();

    float acc[4][4][4];
    #pragma unroll
    for (int i = 0; i < 4; i++)
        #pragma unroll
        for (int j = 0; j < 4; j++)
            #pragma unroll
            for (int r = 0; r < 4; r++) acc[i][j][r] = 0.f;

    conv_pass(tile, Ab, g_wH3[0], mw, nw, lane, acc);

    const int q = lane & 3, g = lane >> 2;
    #pragma unroll
    for (int i = 0; i < 4; i++) {
        int m0 = mw*64 + i*16 + g;
        float bb0 = bias[m0], bb1 = bias[m0 + 8];
        size_t ob = ((size_t)(b*C + m0) << 14) + (size_t)(h0 + nw)*W + w0;
        #pragma unroll
        for (int j = 0; j < 4; j++) {
            int co = j*8 + q*2;
            *(float2*)(g_y1 + ob + co) =
                make_float2(acc[i][j][0] + bb0, acc[i][j][1] + bb0);
            *(float2*)(g_y1 + ob + (8 << 14) + co) =
                make_float2(acc[i][j][2] + bb1, acc[i][j][3] + bb1);
        }
    }
}

// ---------------- merged conv2 + mask: one staged t-tile, two passes ---------
__global__ void __launch_bounds__(256, 2)
conv2m_kernel(const float* __restrict__ b2, const float* __restrict__ bm)
{
    extern __shared__ uint32_t tile[];
    uint4* Ab = (uint4*)(tile + TILE_WORDS);

    const int tid  = threadIdx.x;
    const int lane = tid & 31, wid = tid >> 5;
    const int mw = wid >> 2, nw = wid & 3;
    const int b  = blockIdx.y;
    const int h0 = (blockIdx.x >> 2) << 2;
    const int w0 = (blockIdx.x & 3) << 5;
    const int q = lane & 3, g = lane >> 2;

    const float* mup = g_mu   + b*C;
    const float* rsp = g_rsig + b*C;

    // stage t = leaky(norm(y1)) as fp16
    #pragma unroll 4
    for (int pp = 0; pp < 51; pp++) {
        int idx  = pp*256 + tid;
        int pair = idx / 204;
        int pix  = idx - pair*204;
        int pr = pix / 34, pc = pix - pr*34;
        int ih = h0 + pr - 1, iw = w0 + pc - 1;
        float v0 = 0.f, v1 = 0.f;
        if (((unsigned)ih < (unsigned)H) && ((unsigned)iw < (unsigned)W)) {
            const float* s = g_y1 + ((size_t)(b*C + 2*pair) << 14) + (size_t)ih*W + iw;
            float y0 = s[0], y1v = s[(size_t)1 << 14];
            float t0 = (y0  - mup[2*pair])   * rsp[2*pair];
            float t1 = (y1v - mup[2*pair+1]) * rsp[2*pair+1];
            v0 = (t0 < 0.f) ? 0.2f*t0 : t0;
            v1 = (t1 < 0.f) ? 0.2f*t1 : t1;
        }
        tile[pix*TSTRIDE + pair] = pk2(v0, v1);
    }
    __syncthreads();

    float acc[4][4][4];

    // ---- pass 1: conv2 -> out1 (fp16) ----
    #pragma unroll
    for (int i = 0; i < 4; i++)
        #pragma unroll
        for (int j = 0; j < 4; j++)
            #pragma unroll
            for (int r = 0; r < 4; r++) acc[i][j][r] = 0.f;
    conv_pass(tile, Ab, g_wH3[1], mw, nw, lane, acc);
    #pragma unroll
    for (int i = 0; i < 4; i++) {
        int m0 = mw*64 + i*16 + g;
        float bb0 = b2[m0], bb1 = b2[m0 + 8];
        size_t ob = ((size_t)(b*C + m0) << 14) + (size_t)(h0 + nw)*W + w0;
        #pragma unroll
        for (int j = 0; j < 4; j++) {
            int co = j*8 + q*2;
            *(__half2*)(g_out1 + ob + co) =
                __floats2half2_rn(acc[i][j][0] + bb0, acc[i][j][1] + bb0);
            *(__half2*)(g_out1 + ob + (8 << 14) + co) =
                __floats2half2_rn(acc[i][j][2] + bb1, acc[i][j][3] + bb1);
        }
    }

    // ---- pass 2: mask -> m (fp16), xm = t*m (fp16) ----
    #pragma unroll
    for (int i = 0; i < 4; i++)
        #pragma unroll
        for (int j = 0; j < 4; j++)
            #pragma unroll
            for (int r = 0; r < 4; r++) acc[i][j][r] = 0.f;
    conv_pass(tile, Ab, g_wH3[2], mw, nw, lane, acc);
    #pragma unroll
    for (int i = 0; i < 4; i++) {
        int m0 = mw*64 + i*16 + g;
        int mh = m0 >> 1;
        int par = m0 & 1;
        float bb0 = bm[m0], bb1 = bm[m0 + 8];
        size_t ob = ((size_t)(b*C + m0) << 14) + (size_t)(h0 + nw)*W + w0;
        #pragma unroll
        for (int j = 0; j < 4; j++) {
            int co = j*8 + q*2;
            int pix = (nw + 1)*34 + co + 1;
            uint32_t wa0 = tile[ pix     *TSTRIDE + mh];
            uint32_t wa1 = tile[(pix + 1)*TSTRIDE + mh];
            uint32_t wb0 = tile[ pix     *TSTRIDE + mh + 4];
            uint32_t wb1 = tile[(pix + 1)*TSTRIDE + mh + 4];
            float t00 = par ? h2hi(wa0) : h2lo(wa0);
            float t01 = par ? h2hi(wa1) : h2lo(wa1);
            float t10 = par ? h2hi(wb0) : h2lo(wb0);
            float t11 = par ? h2hi(wb1) : h2lo(wb1);
            float s0 = 1.f/(1.f + __expf(-(acc[i][j][0] + bb0)));
            float s1 = 1.f/(1.f + __expf(-(acc[i][j][1] + bb0)));
            float s2 = 1.f/(1.f + __expf(-(acc[i][j][2] + bb1)));
            float s3 = 1.f/(1.f + __expf(-(acc[i][j][3] + bb1)));
            *(__half2*)(g_m + ob + co)             = __floats2half2_rn(s0, s1);
            *(__half2*)(g_m + ob + (8 << 14) + co) = __floats2half2_rn(s2, s3);
            *(__half2*)(g_xm + ob + co)             = __floats2half2_rn(s0*t00, s1*t01);
            *(__half2*)(g_xm + ob + (8 << 14) + co) = __floats2half2_rn(s2*t10, s3*t11);
        }
    }
}

// ---------------- merged q/k/v 1x1 GEMM (fp16 in/out) ------------------------
#define BP 136
__global__ void __launch_bounds__(256, 2)
conv_qkv(const float* __restrict__ bq, const float* __restrict__ bk,
         const float* __restrict__ bv_)
{
    __shared__ uint32_t Bsq[8][8*BP];
    __shared__ uint4    Asq[2][256];

    const int tid  = threadIdx.x;
    const int lane = tid & 31, wid = tid >> 5;
    const int mw = wid >> 2, nw = wid & 3;
    const int b  = blockIdx.y;
    const int h0 = (blockIdx.x >> 2) << 2;
    const int w0 = (blockIdx.x & 3) << 5;

    const int sub  = tid >> 7;
    const int nn   = tid & 127;
    const int prow = nn >> 5, pcol = nn & 31;

    const uint32_t aBase = smem_u32(&Asq[0][0]);
    auto cpA = [&](const uint4* wA, int r, int buf) {
        CP_ASYNC16(aBase + ((buf*256 + tid) << 4), wA + (size_t)r*256 + tid);
        CP_COMMIT();
    };

    {
        const __half* src0 = g_xm + ((size_t)(b*C) << 14)
                           + (size_t)(h0 + prow)*W + (w0 + pcol);
        #pragma unroll
        for (int ks = 0; ks < 8; ks++) {
            const __half* src = src0 + ((size_t)(ks*16 + sub*8) << 14);
            __half vb[8];
            #pragma unroll
            for (int j = 0; j < 8; j++)
                vb[j] = src[(size_t)j << 14];
            #pragma unroll
            for (int p = 0; p < 4; p++)
                Bsq[ks][(sub*4 + p)*BP + nn] = pkh(vb[2*p], vb[2*p + 1]);
        }
    }

    for (int set = 0; set < 3; set++) {
        const uint4* wA = g_wH1[set];
        const float* bias = (set == 0) ? bq : (set == 1) ? bk : bv_;
        __half* out = (set == 0) ? g_q : (set == 1) ? g_k : g_v;

        float acc[4][4][4];
        #pragma unroll
        for (int i = 0; i < 4; i++)
            #pragma unroll
            for (int j = 0; j < 4; j++)
                #pragma unroll
                for (int r = 0; r < 4; r++) acc[i][j][r] = 0.f;

        cpA(wA, 0, 0);
        CP_WAIT0();
        __syncthreads();

        for (int r = 0; r < 8; r++) {
            int buf = r & 1;
            if (r + 1 < 8) cpA(wA, r + 1, buf ^ 1);
            uint4 af[4];
            #pragma unroll
            for (int i = 0; i < 4; i++)
                af[i] = Asq[buf][(mw*4 + i)*32 + lane];
            uint32_t bf[4][2];
            const int q = lane & 3;
            #pragma unroll
            for (int j = 0; j < 4; j++) {
                int n = nw*32 + j*8 + (lane >> 2);
                bf[j][0] = Bsq[r][ q     *BP + n];
                bf[j][1] = Bsq[r][(4 + q)*BP + n];
            }
            #pragma unroll
            for (int i = 0; i < 4; i++)
                #pragma unroll
                for (int j = 0; j < 4; j++)
                    mma_f16(acc[i][j], (const uint32_t*)&af[i], bf[j]);
            if (r + 1 < 8) {
                CP_WAIT0();
                __syncthreads();
            }
        }

        #pragma unroll
        for (int i = 0; i < 4; i++) {
            int m0 = mw*64 + i*16 + (lane >> 2);
            float bb0 = bias[m0], bb1 = bias[m0 + 8];
            size_t ob = ((size_t)(b*C + m0) << 14) + (size_t)(h0 + nw)*W + w0;
            #pragma unroll
            for (int j = 0; j < 4; j++) {
                int co = j*8 + (lane & 3)*2;
                *(__half2*)(out + ob + co) =
                    __floats2half2_rn(acc[i][j][0] + bb0, acc[i][j][1] + bb0);
                *(__half2*)(out + ob + (8 << 14) + co) =
                    __floats2half2_rn(acc[i][j][2] + bb1, acc[i][j][3] + bb1);
            }
        }
        __syncthreads();
    }
}

// ---------------- local 3x3 attention + blend + residual --------------------
// 8-way channel split (16 ch each), 1 row/CTA, shuffle edge taps; q/k/v/m/out1
// all fp16.
__global__ void __launch_bounds__(256)
attn_kernel(const float* __restrict__ x, const float* __restrict__ k_b,
            const float* __restrict__ v_b, float* __restrict__ out)
{
    __shared__ float att[8][32][37];

    const int b    = blockIdx.y;
    const int tid  = threadIdx.x;
    const int cg   = tid >> 5;
    const int lane = tid & 31;
    const int h    = blockIdx.x;
    const int wq   = lane*4;
    const size_t bbase = (size_t)b*C*HW;
    const int poff = h*W + wq;
    const int c0 = cg*16;

    float sims[9][4];
    #pragma unroll
    for (int o = 0; o < 9; o++)
        #pragma unroll
        for (int p = 0; p < 4; p++) sims[o][p] = 0.f;

    #pragma unroll 2
    for (int ci = 0; ci < 16; ci++) {
        int c = c0 + ci;
        const __half* kp = g_k + bbase + ((size_t)c << 14);
        float kbv = __ldg(k_b + c);
        uint2 qr = *(const uint2*)(g_q + bbase + ((size_t)c << 14) + poff);
        float q[4] = {h2lo(qr.x), h2hi(qr.x), h2lo(qr.y), h2hi(qr.y)};
        #pragma unroll
        for (int dr = 0; dr < 3; dr++) {
            int hh = h + dr - 1;
            bool rok = ((unsigned)hh < (unsigned)H);
            float m0 = kbv, m1 = kbv, m2 = kbv, m3 = kbv;
            if (rok) {
                uint2 kr = *(const uint2*)(kp + hh*W + wq);
                m0 = h2lo(kr.x); m1 = h2hi(kr.x);
                m2 = h2lo(kr.y); m3 = h2hi(kr.y);
            }
            float lf = __shfl_up_sync(0xffffffffu, m3, 1);
            if (lane == 0)  lf = kbv;
            float rt = __shfl_down_sync(0xffffffffu, m0, 1);
            if (lane == 31) rt = kbv;
            float val[6] = {lf, m0, m1, m2, m3, rt};
            #pragma unroll
            for (int dj = 0; dj < 3; dj++)
                #pragma unroll
                for (int p = 0; p < 4; p++)
                    sims[dr*3 + dj][p] = fmaf(q[p], val[p + dj], sims[dr*3 + dj][p]);
        }
    }

    #pragma unroll
    for (int o = 0; o < 9; o++)
        #pragma unroll
        for (int p = 0; p < 4; p++)
            att[cg][lane][o*4 + p] = sims[o][p];
    __syncthreads();

    #pragma unroll
    for (int o = 0; o < 9; o++) {
        #pragma unroll
        for (int p = 0; p < 4; p++) {
            float s = 0.f;
            #pragma unroll
            for (int gr = 0; gr < 8; gr++)
                s += att[gr][lane][o*4 + p];
            sims[o][p] = s;
        }
    }
    #pragma unroll
    for (int p = 0; p < 4; p++) {
        float mx = sims[0][p];
        #pragma unroll
        for (int o = 1; o < 9; o++) mx = fmaxf(mx, sims[o][p]);
        float se = 0.f;
        #pragma unroll
        for (int o = 0; o < 9; o++) { sims[o][p] = __expf(sims[o][p] - mx); se += sims[o][p]; }
        float inv = 1.f / se;
        #pragma unroll
        for (int o = 0; o < 9; o++) sims[o][p] *= inv;
    }

    #pragma unroll 2
    for (int ci = 0; ci < 16; ci++) {
        int c = c0 + ci;
        const __half* vp = g_v + bbase + ((size_t)c << 14);
        float vbv = __ldg(v_b + c);
        float o2[4] = {0.f, 0.f, 0.f, 0.f};
        #pragma unroll
        for (int dr = 0; dr < 3; dr++) {
            int hh = h + dr - 1;
            bool rok = ((unsigned)hh < (unsigned)H);
            float m0 = vbv, m1 = vbv, m2 = vbv, m3 = vbv;
            if (rok) {
                uint2 vr = *(const uint2*)(vp + hh*W + wq);
                m0 = h2lo(vr.x); m1 = h2hi(vr.x);
                m2 = h2lo(vr.y); m3 = h2hi(vr.y);
            }
            float lf = __shfl_up_sync(0xffffffffu, m3, 1);
            if (lane == 0)  lf = vbv;
            float rt = __shfl_down_sync(0xffffffffu, m0, 1);
            if (lane == 31) rt = vbv;
            float val[6] = {lf, m0, m1, m2, m3, rt};
            #pragma unroll
            for (int dj = 0; dj < 3; dj++)
                #pragma unroll
                for (int p = 0; p < 4; p++)
                    o2[p] = fmaf(sims[dr*3 + dj][p], val[p + dj], o2[p]);
        }
        size_t idx = bbase + ((size_t)c << 14) + poff;
        uint2 mraw = *(const uint2*)(g_m    + idx);
        uint2 oraw = *(const uint2*)(g_out1 + idx);
        float4 xv  = *(const float4*)(x     + idx);
        float mv0 = h2lo(mraw.x), mv1 = h2hi(mraw.x);
        float mv2 = h2lo(mraw.y), mv3 = h2hi(mraw.y);
        float o10 = h2lo(oraw.x), o11 = h2hi(oraw.x);
        float o12 = h2lo(oraw.y), o13 = h2hi(oraw.y);
        float4 ov;
        ov.x = xv.x + o10*mv0 + (1.f - mv0)*o2[0];
        ov.y = xv.y + o11*mv1 + (1.f - mv1)*o2[1];
        ov.z = xv.z + o12*mv2 + (1.f - mv2)*o2[2];
        ov.w = xv.w + o13*mv3 + (1.f - mv3)*o2[3];
        *(float4*)(out + idx) = ov;
    }
}

// ---------------- launch ----------------------------------------------------
extern "C" void kernel_launch(void* const* d_in, const int* in_sizes, int n_in,
                              void* d_out, int out_size)
{
    const float* x  = (const float*)d_in[0];
    const float* w1 = (const float*)d_in[1];
    const float* b1 = (const float*)d_in[2];
    const float* w2 = (const float*)d_in[3];
    const float* b2 = (const float*)d_in[4];
    const float* wm = (const float*)d_in[5];
    const float* bm = (const float*)d_in[6];
    const float* wq = (const float*)d_in[7];
    const float* bq = (const float*)d_in[8];
    const float* wk = (const float*)d_in[9];
    const float* bk = (const float*)d_in[10];
    const float* wv = (const float*)d_in[11];
    const float* bv = (const float*)d_in[12];
    float* out = (float*)d_out;

    cudaFuncSetAttribute(conv1_kernel,  cudaFuncAttributeMaxDynamicSharedMemorySize, CONV_SMEM);
    cudaFuncSetAttribute(conv2m_kernel, cudaFuncAttributeMaxDynamicSharedMemorySize, CONV_SMEM);

    pack_weights<<<216, 256>>>(w1, w2, wm, wq, wk, wv);

    dim3 gc(128, BATCH);
    conv1_kernel<<<gc, 256, CONV_SMEM>>>(x, b1);
    stats_kernel<<<BATCH*C, 512>>>();
    conv2m_kernel<<<gc, 256, CONV_SMEM>>>(b2, bm);
    conv_qkv<<<gc, 256>>>(bq, bk, bv);

    dim3 ga(H, BATCH);
    attn_kernel<<<ga, 256>>>(x, bk, bv, out);
}

// round 16
// speedup vs baseline: 1.1542x; 1.0062x over previous
#include <cuda_runtime.h>
#include <cuda_fp16.h>
#include <cstdint>

#define BATCH 8
#define C 128
#define H 128
#define W 128
#define HW (H*W)

// ---------------- scratch (device globals; no allocation allowed) ----------
__device__ float  g_y1  [BATCH*C*HW];   // conv1 raw output
__device__ __half g_out1[BATCH*C*HW];
__device__ __half g_m   [BATCH*C*HW];
__device__ __half g_xm  [BATCH*C*HW];   // t * m
__device__ __half g_q   [BATCH*C*HW];
__device__ __half g_k   [BATCH*C*HW];
__device__ __half g_v   [BATCH*C*HW];
__device__ float  g_mu  [BATCH*C];
__device__ float  g_rsig[BATCH*C];
// fp16 weights packed in per-thread m16n8k16 fragment order
__device__ uint4 g_wH3[3][72*8*32];    // 3x3 convs: [(ks*8+fr)*32+lane]
__device__ uint4 g_wH1[3][8*8*32];     // 1x1 convs

__constant__ int c_di[9] = {-1,-1,-1, 0,0,0, 1,1,1};
__constant__ int c_dj[9] = {-1, 0, 1,-1,0,1,-1,0,1};

__device__ __forceinline__ void mma_f16(float* d, const uint32_t* a, const uint32_t* b) {
    asm volatile(
        "mma.sync.aligned.m16n8k16.row.col.f32.f16.f16.f32 "
        "{%0,%1,%2,%3}, {%4,%5,%6,%7}, {%8,%9}, {%0,%1,%2,%3};"
        : "+f"(d[0]), "+f"(d[1]), "+f"(d[2]), "+f"(d[3])
        : "r"(a[0]), "r"(a[1]), "r"(a[2]), "r"(a[3]), "r"(b[0]), "r"(b[1]));
}
__device__ __forceinline__ uint32_t smem_u32(const void* p) {
    uint32_t a;
    asm("{ .reg .u64 t; cvta.to.shared.u64 t, %1; cvt.u32.u64 %0, t; }"
        : "=r"(a) : "l"(p));
    return a;
}
__device__ __forceinline__ uint32_t pk2(float lo, float hi) {
    __half2 h = __floats2half2_rn(lo, hi);
    return *(uint32_t*)&h;
}
__device__ __forceinline__ uint32_t pkh(__half lo, __half hi) {
    __half2 h = __halves2half2(lo, hi);
    return *(uint32_t*)&h;
}
__device__ __forceinline__ float h2lo(uint32_t w) {
    return __low2float(*(__half2*)&w);
}
__device__ __forceinline__ float h2hi(uint32_t w) {
    return __high2float(*(__half2*)&w);
}
#define CP_ASYNC16(dst, src) \
    asm volatile("cp.async.ca.shared.global [%0], [%1], 16;" :: "r"(dst), "l"(src))
#define CP_COMMIT() asm volatile("cp.async.commit_group;")
#define CP_WAIT0()  asm volatile("cp.async.wait_group 0;" ::: "memory")
#define CP_WAIT1()  asm volatile("cp.async.wait_group 1;" ::: "memory")

// ---------------- weight packing (fp16 fragment order) ----------------------
__global__ void pack_weights(const float* __restrict__ w1, const float* __restrict__ w2,
                             const float* __restrict__ wm, const float* __restrict__ wq,
                             const float* __restrict__ wk, const float* __restrict__ wv)
{
    int idx = blockIdx.x * blockDim.x + threadIdx.x;
    int lane = idx & 31;
    int fr   = (idx >> 5) & 7;
    int rest = idx >> 8;
    {
        int ks   = rest % 72;
        int conv = rest / 72;
        if (conv < 3) {
            const float* w = (conv == 0) ? w1 : (conv == 1) ? w2 : wm;
            int m0  = fr*16 + (lane >> 2);
            int kq  = lane & 3;
            int tap = ks >> 3;
            int cb  = (ks & 7) << 4;
            int ca  = cb + 2*kq;
            int cc  = cb + 8 + 2*kq;
            uint4 o;
            o.x = pk2(w[ m0   *1152 + ca*9 + tap], w[ m0   *1152 + (ca+1)*9 + tap]);
            o.y = pk2(w[(m0+8)*1152 + ca*9 + tap], w[(m0+8)*1152 + (ca+1)*9 + tap]);
            o.z = pk2(w[ m0   *1152 + cc*9 + tap], w[ m0   *1152 + (cc+1)*9 + tap]);
            o.w = pk2(w[(m0+8)*1152 + cc*9 + tap], w[(m0+8)*1152 + (cc+1)*9 + tap]);
            g_wH3[conv][(ks*8 + fr)*32 + lane] = o;
        }
    }
    if (idx < 3*8*8*32) {
        int ks  = rest % 8;
        int set = rest / 8;
        const float* w = (set == 0) ? wq : (set == 1) ? wk : wv;
        int m0 = fr*16 + (lane >> 2);
        int kq = lane & 3;
        int cb = ks << 4;
        int ca = cb + 2*kq;
        int cc = cb + 8 + 2*kq;
        uint4 o;
        o.x = pk2(w[ m0   *128 + ca], w[ m0   *128 + ca+1]);
        o.y = pk2(w[(m0+8)*128 + ca], w[(m0+8)*128 + ca+1]);
        o.z = pk2(w[ m0   *128 + cc], w[ m0   *128 + cc+1]);
        o.w = pk2(w[(m0+8)*128 + cc], w[(m0+8)*128 + cc+1]);
        g_wH1[set][(ks*8 + fr)*32 + lane] = o;
    }
}

// ---------------- stats only (mu, rsig per (b,c)) ----------------------------
__global__ void __launch_bounds__(512)
stats_kernel()
{
    int bc = blockIdx.x;
    const float4* p = (const float4*)(g_y1 + (size_t)bc * HW);
    float s = 0.f, sq = 0.f;
    #pragma unroll
    for (int i = 0; i < 8; i++) {
        float4 v = p[threadIdx.x + 512*i];
        s  += (v.x + v.y) + (v.z + v.w);
        sq += v.x*v.x + v.y*v.y + v.z*v.z + v.w*v.w;
    }
    #pragma unroll
    for (int o = 16; o; o >>= 1) {
        s  += __shfl_xor_sync(0xffffffffu, s,  o);
        sq += __shfl_xor_sync(0xffffffffu, sq, o);
    }
    __shared__ float ss[16], sqq[16];
    int wrp = threadIdx.x >> 5;
    if ((threadIdx.x & 31) == 0) { ss[wrp] = s; sqq[wrp] = sq; }
    __syncthreads();
    if (threadIdx.x == 0) {
        float S = 0.f, Q = 0.f;
        #pragma unroll
        for (int i = 0; i < 16; i++) { S += ss[i]; Q += sqq[i]; }
        float mu  = S / (float)HW;
        float var = Q / (float)HW - mu*mu;
        g_mu[bc]   = mu;
        g_rsig[bc] = rsqrtf(var + 1e-5f);
    }
}

// ---------------- fp16 3x3 conv core (B-stationary tile, 3-stage A ring) ----
#define TPIX 204
#define TSTRIDE 68
#define TILE_WORDS (TPIX*TSTRIDE)            // 13872
#define A_HT 1024                            // uint4 per half-tap (4 steps)
#define CONV_SMEM (TILE_WORDS*4 + 3*A_HT*16) // 55488 + 49152 = 104640 B

__device__ __forceinline__ void conv_pass(const uint32_t* tile, uint4* Ab,
                                          const uint4* wA, int mw, int nw,
                                          int lane, float acc[4][4][4])
{
    const int q = lane & 3, g = lane >> 2;
    const int tid = threadIdx.x;
    const uint32_t aBase = smem_u32(Ab);

    auto issue = [&](int hs) {
        int buf = hs % 3;
        const uint4* src = wA + hs*A_HT + tid;
        uint32_t d = aBase + ((buf*A_HT + tid) << 4);
        CP_ASYNC16(d,              src);
        CP_ASYNC16(d + (256 << 4), src + 256);
        CP_ASYNC16(d + (512 << 4), src + 512);
        CP_ASYNC16(d + (768 << 4), src + 768);
        CP_COMMIT();
    };

    issue(0);
    issue(1);
    for (int hs = 0; hs < 18; hs++) {
        if (hs + 1 < 18) CP_WAIT1();   // stage hs landed; hs+1 may be in flight
        else             CP_WAIT0();
        __syncthreads();               // publish stage hs; recycle buf (hs+2)%3

        int tap = hs >> 1;
        const uint32_t* bp = tile
            + ((nw + c_di[tap] + 1)*34 + c_dj[tap] + 1 + g)*TSTRIDE
            + q + (hs & 1)*32;
        const uint4* ap = Ab + (hs % 3)*A_HT + (mw*4)*32 + lane;
        #pragma unroll
        for (int s = 0; s < 4; s++) {
            uint4 aC[4];
            #pragma unroll
            for (int i = 0; i < 4; i++)
                aC[i] = ap[(s*8 + i)*32];
            uint32_t bf[4][2];
            #pragma unroll
            for (int j = 0; j < 4; j++) {
                bf[j][0] = bp[j*8*TSTRIDE + s*8];
                bf[j][1] = bp[j*8*TSTRIDE + s*8 + 4];
            }
            #pragma unroll
            for (int i = 0; i < 4; i++)
                #pragma unroll
                for (int j = 0; j < 4; j++)
                    mma_f16(acc[i][j], (const uint32_t*)&aC[i], bf[j]);
        }
        if (hs + 2 < 18) issue(hs + 2);
    }
}

// ---------------- conv1: raw x -> y1 -----------------------------------------
__global__ void __launch_bounds__(256, 2)
conv1_kernel(const float* __restrict__ in, const float* __restrict__ bias)
{
    extern __shared__ uint32_t tile[];
    uint4* Ab = (uint4*)(tile + TILE_WORDS);

    const int tid  = threadIdx.x;
    const int lane = tid & 31, wid = tid >> 5;
    const int mw = wid >> 2, nw = wid & 3;
    const int b  = blockIdx.y;
    const int h0 = (blockIdx.x >> 2) << 2;
    const int w0 = (blockIdx.x & 3) << 5;

    #pragma unroll 4
    for (int pp = 0; pp < 51; pp++) {
        int idx  = pp*256 + tid;
        int pair = idx / 204;
        int pix  = idx - pair*204;
        int pr = pix / 34, pc = pix - pr*34;
        int ih = h0 + pr - 1, iw = w0 + pc - 1;
        float v0 = 0.f, v1 = 0.f;
        if (((unsigned)ih < (unsigned)H) && ((unsigned)iw < (unsigned)W)) {
            const float* s = in + ((size_t)(b*C + 2*pair) << 14) + (size_t)ih*W + iw;
            v0 = s[0];
            v1 = s[(size_t)1 << 14];
        }
        tile[pix*TSTRIDE + pair] = pk2(v0, v1);
    }
    __syncthreads();

    float acc[4][4][4];
    #pragma unroll
    for (int i = 0; i < 4; i++)
        #pragma unroll
        for (int j = 0; j < 4; j++)
            #pragma unroll
            for (int r = 0; r < 4; r++) acc[i][j][r] = 0.f;

    conv_pass(tile, Ab, g_wH3[0], mw, nw, lane, acc);

    const int q = lane & 3, g = lane >> 2;
    #pragma unroll
    for (int i = 0; i < 4; i++) {
        int m0 = mw*64 + i*16 + g;
        float bb0 = bias[m0], bb1 = bias[m0 + 8];
        size_t ob = ((size_t)(b*C + m0) << 14) + (size_t)(h0 + nw)*W + w0;
        #pragma unroll
        for (int j = 0; j < 4; j++) {
            int co = j*8 + q*2;
            *(float2*)(g_y1 + ob + co) =
                make_float2(acc[i][j][0] + bb0, acc[i][j][1] + bb0);
            *(float2*)(g_y1 + ob + (8 << 14) + co) =
                make_float2(acc[i][j][2] + bb1, acc[i][j][3] + bb1);
        }
    }
}

// ---------------- merged conv2 + mask: one staged t-tile, two passes ---------
__global__ void __launch_bounds__(256, 2)
conv2m_kernel(const float* __restrict__ b2, const float* __restrict__ bm)
{
    extern __shared__ uint32_t tile[];
    uint4* Ab = (uint4*)(tile + TILE_WORDS);

    const int tid  = threadIdx.x;
    const int lane = tid & 31, wid = tid >> 5;
    const int mw = wid >> 2, nw = wid & 3;
    const int b  = blockIdx.y;
    const int h0 = (blockIdx.x >> 2) << 2;
    const int w0 = (blockIdx.x & 3) << 5;
    const int q = lane & 3, g = lane >> 2;

    const float* mup = g_mu   + b*C;
    const float* rsp = g_rsig + b*C;

    // stage t = leaky(norm(y1)) as fp16
    #pragma unroll 4
    for (int pp = 0; pp < 51; pp++) {
        int idx  = pp*256 + tid;
        int pair = idx / 204;
        int pix  = idx - pair*204;
        int pr = pix / 34, pc = pix - pr*34;
        int ih = h0 + pr - 1, iw = w0 + pc - 1;
        float v0 = 0.f, v1 = 0.f;
        if (((unsigned)ih < (unsigned)H) && ((unsigned)iw < (unsigned)W)) {
            const float* s = g_y1 + ((size_t)(b*C + 2*pair) << 14) + (size_t)ih*W + iw;
            float y0 = s[0], y1v = s[(size_t)1 << 14];
            float t0 = (y0  - mup[2*pair])   * rsp[2*pair];
            float t1 = (y1v - mup[2*pair+1]) * rsp[2*pair+1];
            v0 = (t0 < 0.f) ? 0.2f*t0 : t0;
            v1 = (t1 < 0.f) ? 0.2f*t1 : t1;
        }
        tile[pix*TSTRIDE + pair] = pk2(v0, v1);
    }
    __syncthreads();

    float acc[4][4][4];

    // ---- pass 1: conv2 -> out1 (fp16) ----
    #pragma unroll
    for (int i = 0; i < 4; i++)
        #pragma unroll
        for (int j = 0; j < 4; j++)
            #pragma unroll
            for (int r = 0; r < 4; r++) acc[i][j][r] = 0.f;
    conv_pass(tile, Ab, g_wH3[1], mw, nw, lane, acc);
    #pragma unroll
    for (int i = 0; i < 4; i++) {
        int m0 = mw*64 + i*16 + g;
        float bb0 = b2[m0], bb1 = b2[m0 + 8];
        size_t ob = ((size_t)(b*C + m0) << 14) + (size_t)(h0 + nw)*W + w0;
        #pragma unroll
        for (int j = 0; j < 4; j++) {
            int co = j*8 + q*2;
            *(__half2*)(g_out1 + ob + co) =
                __floats2half2_rn(acc[i][j][0] + bb0, acc[i][j][1] + bb0);
            *(__half2*)(g_out1 + ob + (8 << 14) + co) =
                __floats2half2_rn(acc[i][j][2] + bb1, acc[i][j][3] + bb1);
        }
    }

    // ---- pass 2: mask -> m (fp16), xm = t*m (fp16) ----
    #pragma unroll
    for (int i = 0; i < 4; i++)
        #pragma unroll
        for (int j = 0; j < 4; j++)
            #pragma unroll
            for (int r = 0; r < 4; r++) acc[i][j][r] = 0.f;
    conv_pass(tile, Ab, g_wH3[2], mw, nw, lane, acc);
    #pragma unroll
    for (int i = 0; i < 4; i++) {
        int m0 = mw*64 + i*16 + g;
        int mh = m0 >> 1;
        int par = m0 & 1;
        float bb0 = bm[m0], bb1 = bm[m0 + 8];
        size_t ob = ((size_t)(b*C + m0) << 14) + (size_t)(h0 + nw)*W + w0;
        #pragma unroll
        for (int j = 0; j < 4; j++) {
            int co = j*8 + q*2;
            int pix = (nw + 1)*34 + co + 1;
            uint32_t wa0 = tile[ pix     *TSTRIDE + mh];
            uint32_t wa1 = tile[(pix + 1)*TSTRIDE + mh];
            uint32_t wb0 = tile[ pix     *TSTRIDE + mh + 4];
            uint32_t wb1 = tile[(pix + 1)*TSTRIDE + mh + 4];
            float t00 = par ? h2hi(wa0) : h2lo(wa0);
            float t01 = par ? h2hi(wa1) : h2lo(wa1);
            float t10 = par ? h2hi(wb0) : h2lo(wb0);
            float t11 = par ? h2hi(wb1) : h2lo(wb1);
            float s0 = 1.f/(1.f + __expf(-(acc[i][j][0] + bb0)));
            float s1 = 1.f/(1.f + __expf(-(acc[i][j][1] + bb0)));
            float s2 = 1.f/(1.f + __expf(-(acc[i][j][2] + bb1)));
            float s3 = 1.f/(1.f + __expf(-(acc[i][j][3] + bb1)));
            *(__half2*)(g_m + ob + co)             = __floats2half2_rn(s0, s1);
            *(__half2*)(g_m + ob + (8 << 14) + co) = __floats2half2_rn(s2, s3);
            *(__half2*)(g_xm + ob + co)             = __floats2half2_rn(s0*t00, s1*t01);
            *(__half2*)(g_xm + ob + (8 << 14) + co) = __floats2half2_rn(s2*t10, s3*t11);
        }
    }
}

// ---------------- merged q/k/v 1x1 GEMM (fp16 in/out) ------------------------
#define BP 136
__global__ void __launch_bounds__(256, 2)
conv_qkv(const float* __restrict__ bq, const float* __restrict__ bk,
         const float* __restrict__ bv_)
{
    __shared__ uint32_t Bsq[8][8*BP];
    __shared__ uint4    Asq[2][256];

    const int tid  = threadIdx.x;
    const int lane = tid & 31, wid = tid >> 5;
    const int mw = wid >> 2, nw = wid & 3;
    const int b  = blockIdx.y;
    const int h0 = (blockIdx.x >> 2) << 2;
    const int w0 = (blockIdx.x & 3) << 5;

    const int sub  = tid >> 7;
    const int nn   = tid & 127;
    const int prow = nn >> 5, pcol = nn & 31;

    const uint32_t aBase = smem_u32(&Asq[0][0]);
    auto cpA = [&](const uint4* wA, int r, int buf) {
        CP_ASYNC16(aBase + ((buf*256 + tid) << 4), wA + (size_t)r*256 + tid);
        CP_COMMIT();
    };

    {
        const __half* src0 = g_xm + ((size_t)(b*C) << 14)
                           + (size_t)(h0 + prow)*W + (w0 + pcol);
        #pragma unroll
        for (int ks = 0; ks < 8; ks++) {
            const __half* src = src0 + ((size_t)(ks*16 + sub*8) << 14);
            __half vb[8];
            #pragma unroll
            for (int j = 0; j < 8; j++)
                vb[j] = src[(size_t)j << 14];
            #pragma unroll
            for (int p = 0; p < 4; p++)
                Bsq[ks][(sub*4 + p)*BP + nn] = pkh(vb[2*p], vb[2*p + 1]);
        }
    }

    for (int set = 0; set < 3; set++) {
        const uint4* wA = g_wH1[set];
        const float* bias = (set == 0) ? bq : (set == 1) ? bk : bv_;
        __half* out = (set == 0) ? g_q : (set == 1) ? g_k : g_v;

        float acc[4][4][4];
        #pragma unroll
        for (int i = 0; i < 4; i++)
            #pragma unroll
            for (int j = 0; j < 4; j++)
                #pragma unroll
                for (int r = 0; r < 4; r++) acc[i][j][r] = 0.f;

        cpA(wA, 0, 0);
        CP_WAIT0();
        __syncthreads();

        for (int r = 0; r < 8; r++) {
            int buf = r & 1;
            if (r + 1 < 8) cpA(wA, r + 1, buf ^ 1);
            uint4 af[4];
            #pragma unroll
            for (int i = 0; i < 4; i++)
                af[i] = Asq[buf][(mw*4 + i)*32 + lane];
            uint32_t bf[4][2];
            const int q = lane & 3;
            #pragma unroll
            for (int j = 0; j < 4; j++) {
                int n = nw*32 + j*8 + (lane >> 2);
                bf[j][0] = Bsq[r][ q     *BP + n];
                bf[j][1] = Bsq[r][(4 + q)*BP + n];
            }
            #pragma unroll
            for (int i = 0; i < 4; i++)
                #pragma unroll
                for (int j = 0; j < 4; j++)
                    mma_f16(acc[i][j], (const uint32_t*)&af[i], bf[j]);
            if (r + 1 < 8) {
                CP_WAIT0();
                __syncthreads();
            }
        }

        #pragma unroll
        for (int i = 0; i < 4; i++) {
            int m0 = mw*64 + i*16 + (lane >> 2);
            float bb0 = bias[m0], bb1 = bias[m0 + 8];
            size_t ob = ((size_t)(b*C + m0) << 14) + (size_t)(h0 + nw)*W + w0;
            #pragma unroll
            for (int j = 0; j < 4; j++) {
                int co = j*8 + (lane & 3)*2;
                *(__half2*)(out + ob + co) =
                    __floats2half2_rn(acc[i][j][0] + bb0, acc[i][j][1] + bb0);
                *(__half2*)(out + ob + (8 << 14) + co) =
                    __floats2half2_rn(acc[i][j][2] + bb1, acc[i][j][3] + bb1);
            }
        }
        __syncthreads();
    }
}

// ---------------- local 3x3 attention + blend + residual --------------------
// 8-way channel split (16 ch each), 1 row/CTA, shuffle edge taps; q/k/v/m/out1
// all fp16.
__global__ void __launch_bounds__(256)
attn_kernel(const float* __restrict__ x, const float* __restrict__ k_b,
            const float* __restrict__ v_b, float* __restrict__ out)
{
    __shared__ float att[8][32][37];

    const int b    = blockIdx.y;
    const int tid  = threadIdx.x;
    const int cg   = tid >> 5;
    const int lane = tid & 31;
    const int h    = blockIdx.x;
    const int wq   = lane*4;
    const size_t bbase = (size_t)b*C*HW;
    const int poff = h*W + wq;
    const int c0 = cg*16;

    float sims[9][4];
    #pragma unroll
    for (int o = 0; o < 9; o++)
        #pragma unroll
        for (int p = 0; p < 4; p++) sims[o][p] = 0.f;

    #pragma unroll 2
    for (int ci = 0; ci < 16; ci++) {
        int c = c0 + ci;
        const __half* kp = g_k + bbase + ((size_t)c << 14);
        float kbv = __ldg(k_b + c);
        uint2 qr = *(const uint2*)(g_q + bbase + ((size_t)c << 14) + poff);
        float q[4] = {h2lo(qr.x), h2hi(qr.x), h2lo(qr.y), h2hi(qr.y)};
        #pragma unroll
        for (int dr = 0; dr < 3; dr++) {
            int hh = h + dr - 1;
            bool rok = ((unsigned)hh < (unsigned)H);
            float m0 = kbv, m1 = kbv, m2 = kbv, m3 = kbv;
            if (rok) {
                uint2 kr = *(const uint2*)(kp + hh*W + wq);
                m0 = h2lo(kr.x); m1 = h2hi(kr.x);
                m2 = h2lo(kr.y); m3 = h2hi(kr.y);
            }
            float lf = __shfl_up_sync(0xffffffffu, m3, 1);
            if (lane == 0)  lf = kbv;
            float rt = __shfl_down_sync(0xffffffffu, m0, 1);
            if (lane == 31) rt = kbv;
            float val[6] = {lf, m0, m1, m2, m3, rt};
            #pragma unroll
            for (int dj = 0; dj < 3; dj++)
                #pragma unroll
                for (int p = 0; p < 4; p++)
                    sims[dr*3 + dj][p] = fmaf(q[p], val[p + dj], sims[dr*3 + dj][p]);
        }
    }

    #pragma unroll
    for (int o = 0; o < 9; o++)
        #pragma unroll
        for (int p = 0; p < 4; p++)
            att[cg][lane][o*4 + p] = sims[o][p];
    __syncthreads();

    #pragma unroll
    for (int o = 0; o < 9; o++) {
        #pragma unroll
        for (int p = 0; p < 4; p++) {
            float s = 0.f;
            #pragma unroll
            for (int gr = 0; gr < 8; gr++)
                s += att[gr][lane][o*4 + p];
            sims[o][p] = s;
        }
    }
    #pragma unroll
    for (int p = 0; p < 4; p++) {
        float mx = sims[0][p];
        #pragma unroll
        for (int o = 1; o < 9; o++) mx = fmaxf(mx, sims[o][p]);
        float se = 0.f;
        #pragma unroll
        for (int o = 0; o < 9; o++) { sims[o][p] = __expf(sims[o][p] - mx); se += sims[o][p]; }
        float inv = 1.f / se;
        #pragma unroll
        for (int o = 0; o < 9; o++) sims[o][p] *= inv;
    }

    #pragma unroll 2
    for (int ci = 0; ci < 16; ci++) {
        int c = c0 + ci;
        const __half* vp = g_v + bbase + ((size_t)c << 14);
        float vbv = __ldg(v_b + c);
        float o2[4] = {0.f, 0.f, 0.f, 0.f};
        #pragma unroll
        for (int dr = 0; dr < 3; dr++) {
            int hh = h + dr - 1;
            bool rok = ((unsigned)hh < (unsigned)H);
            float m0 = vbv, m1 = vbv, m2 = vbv, m3 = vbv;
            if (rok) {
                uint2 vr = *(const uint2*)(vp + hh*W + wq);
                m0 = h2lo(vr.x); m1 = h2hi(vr.x);
                m2 = h2lo(vr.y); m3 = h2hi(vr.y);
            }
            float lf = __shfl_up_sync(0xffffffffu, m3, 1);
            if (lane == 0)  lf = vbv;
            float rt = __shfl_down_sync(0xffffffffu, m0, 1);
            if (lane == 31) rt = vbv;
            float val[6] = {lf, m0, m1, m2, m3, rt};
            #pragma unroll
            for (int dj = 0; dj < 3; dj++)
                #pragma unroll
                for (int p = 0; p < 4; p++)
                    o2[p] = fmaf(sims[dr*3 + dj][p], val[p + dj], o2[p]);
        }
        size_t idx = bbase + ((size_t)c << 14) + poff;
        uint2 mraw = *(const uint2*)(g_m    + idx);
        uint2 oraw = *(const uint2*)(g_out1 + idx);
        float4 xv  = *(const float4*)(x     + idx);
        float mv0 = h2lo(mraw.x), mv1 = h2hi(mraw.x);
        float mv2 = h2lo(mraw.y), mv3 = h2hi(mraw.y);
        float o10 = h2lo(oraw.x), o11 = h2hi(oraw.x);
        float o12 = h2lo(oraw.y), o13 = h2hi(oraw.y);
        float4 ov;
        ov.x = xv.x + o10*mv0 + (1.f - mv0)*o2[0];
        ov.y = xv.y + o11*mv1 + (1.f - mv1)*o2[1];
        ov.z = xv.z + o12*mv2 + (1.f - mv2)*o2[2];
        ov.w = xv.w + o13*mv3 + (1.f - mv3)*o2[3];
        *(float4*)(out + idx) = ov;
    }
}

// ---------------- launch ----------------------------------------------------
extern "C" void kernel_launch(void* const* d_in, const int* in_sizes, int n_in,
                              void* d_out, int out_size)
{
    const float* x  = (const float*)d_in[0];
    const float* w1 = (const float*)d_in[1];
    const float* b1 = (const float*)d_in[2];
    const float* w2 = (const float*)d_in[3];
    const float* b2 = (const float*)d_in[4];
    const float* wm = (const float*)d_in[5];
    const float* bm = (const float*)d_in[6];
    const float* wq = (const float*)d_in[7];
    const float* bq = (const float*)d_in[8];
    const float* wk = (const float*)d_in[9];
    const float* bk = (const float*)d_in[10];
    const float* wv = (const float*)d_in[11];
    const float* bv = (const float*)d_in[12];
    float* out = (float*)d_out;

    cudaFuncSetAttribute(conv1_kernel,  cudaFuncAttributeMaxDynamicSharedMemorySize, CONV_SMEM);
    cudaFuncSetAttribute(conv2m_kernel, cudaFuncAttributeMaxDynamicSharedMemorySize, CONV_SMEM);

    pack_weights<<<216, 256>>>(w1, w2, wm, wq, wk, wv);

    dim3 gc(128, BATCH);
    conv1_kernel<<<gc, 256, CONV_SMEM>>>(x, b1);
    stats_kernel<<<BATCH*C, 512>>>();
    conv2m_kernel<<<gc, 256, CONV_SMEM>>>(b2, bm);
    conv_qkv<<<gc, 256>>>(bq, bk, bv);

    dim3 ga(H, BATCH);
    attn_kernel<<<ga, 256>>>(x, bk, bv, out);
}

// round 17
// speedup vs baseline: 1.1710x; 1.0146x over previous
#include <cuda_runtime.h>
#include <cuda_fp16.h>
#include <cstdint>

#define BATCH 8
#define C 128
#define H 128
#define W 128
#define HW (H*W)

// ---------------- scratch (device globals; no allocation allowed) ----------
__device__ __half g_y1  [BATCH*C*HW];   // conv1 output (fp16)
__device__ __half g_out1[BATCH*C*HW];
__device__ __half g_m   [BATCH*C*HW];
__device__ __half g_xm  [BATCH*C*HW];   // t * m
__device__ __half g_q   [BATCH*C*HW];
__device__ __half g_k   [BATCH*C*HW];
__device__ __half g_v   [BATCH*C*HW];
__device__ float  g_mu  [BATCH*C];
__device__ float  g_rsig[BATCH*C];
// fp16 weights packed in per-thread m16n8k16 fragment order
__device__ uint4 g_wH3[3][72*8*32];    // 3x3 convs: [(ks*8+fr)*32+lane]
__device__ uint4 g_wH1[3][8*8*32];     // 1x1 convs

__constant__ int c_di[9] = {-1,-1,-1, 0,0,0, 1,1,1};
__constant__ int c_dj[9] = {-1, 0, 1,-1,0,1,-1,0,1};

__device__ __forceinline__ void mma_f16(float* d, const uint32_t* a, const uint32_t* b) {
    asm volatile(
        "mma.sync.aligned.m16n8k16.row.col.f32.f16.f16.f32 "
        "{%0,%1,%2,%3}, {%4,%5,%6,%7}, {%8,%9}, {%0,%1,%2,%3};"
        : "+f"(d[0]), "+f"(d[1]), "+f"(d[2]), "+f"(d[3])
        : "r"(a[0]), "r"(a[1]), "r"(a[2]), "r"(a[3]), "r"(b[0]), "r"(b[1]));
}
__device__ __forceinline__ uint32_t smem_u32(const void* p) {
    uint32_t a;
    asm("{ .reg .u64 t; cvta.to.shared.u64 t, %1; cvt.u32.u64 %0, t; }"
        : "=r"(a) : "l"(p));
    return a;
}
__device__ __forceinline__ uint32_t pk2(float lo, float hi) {
    __half2 h = __floats2half2_rn(lo, hi);
    return *(uint32_t*)&h;
}
__device__ __forceinline__ uint32_t pkh(__half lo, __half hi) {
    __half2 h = __halves2half2(lo, hi);
    return *(uint32_t*)&h;
}
__device__ __forceinline__ float h2lo(uint32_t w) {
    return __low2float(*(__half2*)&w);
}
__device__ __forceinline__ float h2hi(uint32_t w) {
    return __high2float(*(__half2*)&w);
}
#define CP_ASYNC16(dst, src) \
    asm volatile("cp.async.ca.shared.global [%0], [%1], 16;" :: "r"(dst), "l"(src))
#define CP_COMMIT() asm volatile("cp.async.commit_group;")
#define CP_WAIT0()  asm volatile("cp.async.wait_group 0;" ::: "memory")
#define CP_WAIT1()  asm volatile("cp.async.wait_group 1;" ::: "memory")

// ---------------- weight packing (fp16 fragment order) ----------------------
__global__ void pack_weights(const float* __restrict__ w1, const float* __restrict__ w2,
                             const float* __restrict__ wm, const float* __restrict__ wq,
                             const float* __restrict__ wk, const float* __restrict__ wv)
{
    int idx = blockIdx.x * blockDim.x + threadIdx.x;
    int lane = idx & 31;
    int fr   = (idx >> 5) & 7;
    int rest = idx >> 8;
    {
        int ks   = rest % 72;
        int conv = rest / 72;
        if (conv < 3) {
            const float* w = (conv == 0) ? w1 : (conv == 1) ? w2 : wm;
            int m0  = fr*16 + (lane >> 2);
            int kq  = lane & 3;
            int tap = ks >> 3;
            int cb  = (ks & 7) << 4;
            int ca  = cb + 2*kq;
            int cc  = cb + 8 + 2*kq;
            uint4 o;
            o.x = pk2(w[ m0   *1152 + ca*9 + tap], w[ m0   *1152 + (ca+1)*9 + tap]);
            o.y = pk2(w[(m0+8)*1152 + ca*9 + tap], w[(m0+8)*1152 + (ca+1)*9 + tap]);
            o.z = pk2(w[ m0   *1152 + cc*9 + tap], w[ m0   *1152 + (cc+1)*9 + tap]);
            o.w = pk2(w[(m0+8)*1152 + cc*9 + tap], w[(m0+8)*1152 + (cc+1)*9 + tap]);
            g_wH3[conv][(ks*8 + fr)*32 + lane] = o;
        }
    }
    if (idx < 3*8*8*32) {
        int ks  = rest % 8;
        int set = rest / 8;
        const float* w = (set == 0) ? wq : (set == 1) ? wk : wv;
        int m0 = fr*16 + (lane >> 2);
        int kq = lane & 3;
        int cb = ks << 4;
        int ca = cb + 2*kq;
        int cc = cb + 8 + 2*kq;
        uint4 o;
        o.x = pk2(w[ m0   *128 + ca], w[ m0   *128 + ca+1]);
        o.y = pk2(w[(m0+8)*128 + ca], w[(m0+8)*128 + ca+1]);
        o.z = pk2(w[ m0   *128 + cc], w[ m0   *128 + cc+1]);
        o.w = pk2(w[(m0+8)*128 + cc], w[(m0+8)*128 + cc+1]);
        g_wH1[set][(ks*8 + fr)*32 + lane] = o;
    }
}

// ---------------- stats only (mu, rsig per (b,c)), fp16 input ----------------
__global__ void __launch_bounds__(512)
stats_kernel()
{
    int bc = blockIdx.x;
    const uint2* p = (const uint2*)(g_y1 + (size_t)bc * HW);   // 4 halves each
    float s = 0.f, sq = 0.f;
    #pragma unroll
    for (int i = 0; i < 8; i++) {
        uint2 v = p[threadIdx.x + 512*i];
        float a0 = h2lo(v.x), a1 = h2hi(v.x), a2 = h2lo(v.y), a3 = h2hi(v.y);
        s  += (a0 + a1) + (a2 + a3);
        sq += a0*a0 + a1*a1 + a2*a2 + a3*a3;
    }
    #pragma unroll
    for (int o = 16; o; o >>= 1) {
        s  += __shfl_xor_sync(0xffffffffu, s,  o);
        sq += __shfl_xor_sync(0xffffffffu, sq, o);
    }
    __shared__ float ss[16], sqq[16];
    int wrp = threadIdx.x >> 5;
    if ((threadIdx.x & 31) == 0) { ss[wrp] = s; sqq[wrp] = sq; }
    __syncthreads();
    if (threadIdx.x == 0) {
        float S = 0.f, Q = 0.f;
        #pragma unroll
        for (int i = 0; i < 16; i++) { S += ss[i]; Q += sqq[i]; }
        float mu  = S / (float)HW;
        float var = Q / (float)HW - mu*mu;
        g_mu[bc]   = mu;
        g_rsig[bc] = rsqrtf(var + 1e-5f);
    }
}

// ---------------- fp16 3x3 conv core (B-stationary tile, 3-stage A ring) ----
#define TPIX 204
#define TSTRIDE 68
#define TILE_WORDS (TPIX*TSTRIDE)            // 13872
#define A_HT 1024                            // uint4 per half-tap (4 steps)
#define CONV_SMEM (TILE_WORDS*4 + 3*A_HT*16) // 55488 + 49152 = 104640 B

__device__ __forceinline__ void conv_pass(const uint32_t* tile, uint4* Ab,
                                          const uint4* wA, int mw, int nw,
                                          int lane, float acc[4][4][4])
{
    const int q = lane & 3, g = lane >> 2;
    const int tid = threadIdx.x;
    const uint32_t aBase = smem_u32(Ab);

    auto issue = [&](int hs) {
        int buf = hs % 3;
        const uint4* src = wA + hs*A_HT + tid;
        uint32_t d = aBase + ((buf*A_HT + tid) << 4);
        CP_ASYNC16(d,              src);
        CP_ASYNC16(d + (256 << 4), src + 256);
        CP_ASYNC16(d + (512 << 4), src + 512);
        CP_ASYNC16(d + (768 << 4), src + 768);
        CP_COMMIT();
    };

    issue(0);
    issue(1);
    for (int hs = 0; hs < 18; hs++) {
        if (hs + 1 < 18) CP_WAIT1();
        else             CP_WAIT0();
        __syncthreads();

        int tap = hs >> 1;
        const uint32_t* bp = tile
            + ((nw + c_di[tap] + 1)*34 + c_dj[tap] + 1 + g)*TSTRIDE
            + q + (hs & 1)*32;
        const uint4* ap = Ab + (hs % 3)*A_HT + (mw*4)*32 + lane;
        #pragma unroll
        for (int s = 0; s < 4; s++) {
            uint4 aC[4];
            #pragma unroll
            for (int i = 0; i < 4; i++)
                aC[i] = ap[(s*8 + i)*32];
            uint32_t bf[4][2];
            #pragma unroll
            for (int j = 0; j < 4; j++) {
                bf[j][0] = bp[j*8*TSTRIDE + s*8];
                bf[j][1] = bp[j*8*TSTRIDE + s*8 + 4];
            }
            #pragma unroll
            for (int i = 0; i < 4; i++)
                #pragma unroll
                for (int j = 0; j < 4; j++)
                    mma_f16(acc[i][j], (const uint32_t*)&aC[i], bf[j]);
        }
        if (hs + 2 < 18) issue(hs + 2);
    }
}

// ---------------- conv1: raw x -> y1 (fp16) ----------------------------------
__global__ void __launch_bounds__(256, 2)
conv1_kernel(const float* __restrict__ in, const float* __restrict__ bias)
{
    extern __shared__ uint32_t tile[];
    uint4* Ab = (uint4*)(tile + TILE_WORDS);

    const int tid  = threadIdx.x;
    const int lane = tid & 31, wid = tid >> 5;
    const int mw = wid >> 2, nw = wid & 3;
    const int b  = blockIdx.y;
    const int h0 = (blockIdx.x >> 2) << 2;
    const int w0 = (blockIdx.x & 3) << 5;

    #pragma unroll 4
    for (int pp = 0; pp < 51; pp++) {
        int idx  = pp*256 + tid;
        int pair = idx / 204;
        int pix  = idx - pair*204;
        int pr = pix / 34, pc = pix - pr*34;
        int ih = h0 + pr - 1, iw = w0 + pc - 1;
        float v0 = 0.f, v1 = 0.f;
        if (((unsigned)ih < (unsigned)H) && ((unsigned)iw < (unsigned)W)) {
            const float* s = in + ((size_t)(b*C + 2*pair) << 14) + (size_t)ih*W + iw;
            v0 = s[0];
            v1 = s[(size_t)1 << 14];
        }
        tile[pix*TSTRIDE + pair] = pk2(v0, v1);
    }
    __syncthreads();

    float acc[4][4][4];
    #pragma unroll
    for (int i = 0; i < 4; i++)
        #pragma unroll
        for (int j = 0; j < 4; j++)
            #pragma unroll
            for (int r = 0; r < 4; r++) acc[i][j][r] = 0.f;

    conv_pass(tile, Ab, g_wH3[0], mw, nw, lane, acc);

    const int q = lane & 3, g = lane >> 2;
    #pragma unroll
    for (int i = 0; i < 4; i++) {
        int m0 = mw*64 + i*16 + g;
        float bb0 = bias[m0], bb1 = bias[m0 + 8];
        size_t ob = ((size_t)(b*C + m0) << 14) + (size_t)(h0 + nw)*W + w0;
        #pragma unroll
        for (int j = 0; j < 4; j++) {
            int co = j*8 + q*2;
            *(__half2*)(g_y1 + ob + co) =
                __floats2half2_rn(acc[i][j][0] + bb0, acc[i][j][1] + bb0);
            *(__half2*)(g_y1 + ob + (8 << 14) + co) =
                __floats2half2_rn(acc[i][j][2] + bb1, acc[i][j][3] + bb1);
        }
    }
}

// ---------------- merged conv2 + mask: one staged t-tile, two passes ---------
__global__ void __launch_bounds__(256, 2)
conv2m_kernel(const float* __restrict__ b2, const float* __restrict__ bm)
{
    extern __shared__ uint32_t tile[];
    uint4* Ab = (uint4*)(tile + TILE_WORDS);

    const int tid  = threadIdx.x;
    const int lane = tid & 31, wid = tid >> 5;
    const int mw = wid >> 2, nw = wid & 3;
    const int b  = blockIdx.y;
    const int h0 = (blockIdx.x >> 2) << 2;
    const int w0 = (blockIdx.x & 3) << 5;
    const int q = lane & 3, g = lane >> 2;

    const float* mup = g_mu   + b*C;
    const float* rsp = g_rsig + b*C;

    // stage t = leaky(norm(y1)) as fp16 (y1 already fp16)
    #pragma unroll 4
    for (int pp = 0; pp < 51; pp++) {
        int idx  = pp*256 + tid;
        int pair = idx / 204;
        int pix  = idx - pair*204;
        int pr = pix / 34, pc = pix - pr*34;
        int ih = h0 + pr - 1, iw = w0 + pc - 1;
        float v0 = 0.f, v1 = 0.f;
        if (((unsigned)ih < (unsigned)H) && ((unsigned)iw < (unsigned)W)) {
            const __half* s = g_y1 + ((size_t)(b*C + 2*pair) << 14) + (size_t)ih*W + iw;
            float y0  = __half2float(s[0]);
            float y1v = __half2float(s[(size_t)1 << 14]);
            float t0 = (y0  - mup[2*pair])   * rsp[2*pair];
            float t1 = (y1v - mup[2*pair+1]) * rsp[2*pair+1];
            v0 = (t0 < 0.f) ? 0.2f*t0 : t0;
            v1 = (t1 < 0.f) ? 0.2f*t1 : t1;
        }
        tile[pix*TSTRIDE + pair] = pk2(v0, v1);
    }
    __syncthreads();

    float acc[4][4][4];

    // ---- pass 1: conv2 -> out1 (fp16) ----
    #pragma unroll
    for (int i = 0; i < 4; i++)
        #pragma unroll
        for (int j = 0; j < 4; j++)
            #pragma unroll
            for (int r = 0; r < 4; r++) acc[i][j][r] = 0.f;
    conv_pass(tile, Ab, g_wH3[1], mw, nw, lane, acc);
    #pragma unroll
    for (int i = 0; i < 4; i++) {
        int m0 = mw*64 + i*16 + g;
        float bb0 = b2[m0], bb1 = b2[m0 + 8];
        size_t ob = ((size_t)(b*C + m0) << 14) + (size_t)(h0 + nw)*W + w0;
        #pragma unroll
        for (int j = 0; j < 4; j++) {
            int co = j*8 + q*2;
            *(__half2*)(g_out1 + ob + co) =
                __floats2half2_rn(acc[i][j][0] + bb0, acc[i][j][1] + bb0);
            *(__half2*)(g_out1 + ob + (8 << 14) + co) =
                __floats2half2_rn(acc[i][j][2] + bb1, acc[i][j][3] + bb1);
        }
    }

    // ---- pass 2: mask -> m (fp16), xm = t*m (fp16) ----
    #pragma unroll
    for (int i = 0; i < 4; i++)
        #pragma unroll
        for (int j = 0; j < 4; j++)
            #pragma unroll
            for (int r = 0; r < 4; r++) acc[i][j][r] = 0.f;
    conv_pass(tile, Ab, g_wH3[2], mw, nw, lane, acc);
    #pragma unroll
    for (int i = 0; i < 4; i++) {
        int m0 = mw*64 + i*16 + g;
        int mh = m0 >> 1;
        int par = m0 & 1;
        float bb0 = bm[m0], bb1 = bm[m0 + 8];
        size_t ob = ((size_t)(b*C + m0) << 14) + (size_t)(h0 + nw)*W + w0;
        #pragma unroll
        for (int j = 0; j < 4; j++) {
            int co = j*8 + q*2;
            int pix = (nw + 1)*34 + co + 1;
            uint32_t wa0 = tile[ pix     *TSTRIDE + mh];
            uint32_t wa1 = tile[(pix + 1)*TSTRIDE + mh];
            uint32_t wb0 = tile[ pix     *TSTRIDE + mh + 4];
            uint32_t wb1 = tile[(pix + 1)*TSTRIDE + mh + 4];
            float t00 = par ? h2hi(wa0) : h2lo(wa0);
            float t01 = par ? h2hi(wa1) : h2lo(wa1);
            float t10 = par ? h2hi(wb0) : h2lo(wb0);
            float t11 = par ? h2hi(wb1) : h2lo(wb1);
            float s0 = 1.f/(1.f + __expf(-(acc[i][j][0] + bb0)));
            float s1 = 1.f/(1.f + __expf(-(acc[i][j][1] + bb0)));
            float s2 = 1.f/(1.f + __expf(-(acc[i][j][2] + bb1)));
            float s3 = 1.f/(1.f + __expf(-(acc[i][j][3] + bb1)));
            *(__half2*)(g_m + ob + co)             = __floats2half2_rn(s0, s1);
            *(__half2*)(g_m + ob + (8 << 14) + co) = __floats2half2_rn(s2, s3);
            *(__half2*)(g_xm + ob + co)             = __floats2half2_rn(s0*t00, s1*t01);
            *(__half2*)(g_xm + ob + (8 << 14) + co) = __floats2half2_rn(s2*t10, s3*t11);
        }
    }
}

// ---------------- merged q/k/v 1x1 GEMM (fp16 in/out) ------------------------
#define BP 136
__global__ void __launch_bounds__(256, 2)
conv_qkv(const float* __restrict__ bq, const float* __restrict__ bk,
         const float* __restrict__ bv_)
{
    __shared__ uint32_t Bsq[8][8*BP];
    __shared__ uint4    Asq[2][256];

    const int tid  = threadIdx.x;
    const int lane = tid & 31, wid = tid >> 5;
    const int mw = wid >> 2, nw = wid & 3;
    const int b  = blockIdx.y;
    const int h0 = (blockIdx.x >> 2) << 2;
    const int w0 = (blockIdx.x & 3) << 5;

    const int sub  = tid >> 7;
    const int nn   = tid & 127;
    const int prow = nn >> 5, pcol = nn & 31;

    const uint32_t aBase = smem_u32(&Asq[0][0]);
    auto cpA = [&](const uint4* wA, int r, int buf) {
        CP_ASYNC16(aBase + ((buf*256 + tid) << 4), wA + (size_t)r*256 + tid);
        CP_COMMIT();
    };

    {
        const __half* src0 = g_xm + ((size_t)(b*C) << 14)
                           + (size_t)(h0 + prow)*W + (w0 + pcol);
        #pragma unroll
        for (int ks = 0; ks < 8; ks++) {
            const __half* src = src0 + ((size_t)(ks*16 + sub*8) << 14);
            __half vb[8];
            #pragma unroll
            for (int j = 0; j < 8; j++)
                vb[j] = src[(size_t)j << 14];
            #pragma unroll
            for (int p = 0; p < 4; p++)
                Bsq[ks][(sub*4 + p)*BP + nn] = pkh(vb[2*p], vb[2*p + 1]);
        }
    }

    for (int set = 0; set < 3; set++) {
        const uint4* wA = g_wH1[set];
        const float* bias = (set == 0) ? bq : (set == 1) ? bk : bv_;
        __half* out = (set == 0) ? g_q : (set == 1) ? g_k : g_v;

        float acc[4][4][4];
        #pragma unroll
        for (int i = 0; i < 4; i++)
            #pragma unroll
            for (int j = 0; j < 4; j++)
                #pragma unroll
                for (int r = 0; r < 4; r++) acc[i][j][r] = 0.f;

        cpA(wA, 0, 0);
        CP_WAIT0();
        __syncthreads();

        for (int r = 0; r < 8; r++) {
            int buf = r & 1;
            if (r + 1 < 8) cpA(wA, r + 1, buf ^ 1);
            uint4 af[4];
            #pragma unroll
            for (int i = 0; i < 4; i++)
                af[i] = Asq[buf][(mw*4 + i)*32 + lane];
            uint32_t bf[4][2];
            const int q = lane & 3;
            #pragma unroll
            for (int j = 0; j < 4; j++) {
                int n = nw*32 + j*8 + (lane >> 2);
                bf[j][0] = Bsq[r][ q     *BP + n];
                bf[j][1] = Bsq[r][(4 + q)*BP + n];
            }
            #pragma unroll
            for (int i = 0; i < 4; i++)
                #pragma unroll
                for (int j = 0; j < 4; j++)
                    mma_f16(acc[i][j], (const uint32_t*)&af[i], bf[j]);
            if (r + 1 < 8) {
                CP_WAIT0();
                __syncthreads();
            }
        }

        #pragma unroll
        for (int i = 0; i < 4; i++) {
            int m0 = mw*64 + i*16 + (lane >> 2);
            float bb0 = bias[m0], bb1 = bias[m0 + 8];
            size_t ob = ((size_t)(b*C + m0) << 14) + (size_t)(h0 + nw)*W + w0;
            #pragma unroll
            for (int j = 0; j < 4; j++) {
                int co = j*8 + (lane & 3)*2;
                *(__half2*)(out + ob + co) =
                    __floats2half2_rn(acc[i][j][0] + bb0, acc[i][j][1] + bb0);
                *(__half2*)(out + ob + (8 << 14) + co) =
                    __floats2half2_rn(acc[i][j][2] + bb1, acc[i][j][3] + bb1);
            }
        }
        __syncthreads();
    }
}

// ---------------- local 3x3 attention + blend + residual --------------------
__global__ void __launch_bounds__(256)
attn_kernel(const float* __restrict__ x, const float* __restrict__ k_b,
            const float* __restrict__ v_b, float* __restrict__ out)
{
    __shared__ float att[8][32][37];

    const int b    = blockIdx.y;
    const int tid  = threadIdx.x;
    const int cg   = tid >> 5;
    const int lane = tid & 31;
    const int h    = blockIdx.x;
    const int wq   = lane*4;
    const size_t bbase = (size_t)b*C*HW;
    const int poff = h*W + wq;
    const int c0 = cg*16;

    float sims[9][4];
    #pragma unroll
    for (int o = 0; o < 9; o++)
        #pragma unroll
        for (int p = 0; p < 4; p++) sims[o][p] = 0.f;

    #pragma unroll 2
    for (int ci = 0; ci < 16; ci++) {
        int c = c0 + ci;
        const __half* kp = g_k + bbase + ((size_t)c << 14);
        float kbv = __ldg(k_b + c);
        uint2 qr = *(const uint2*)(g_q + bbase + ((size_t)c << 14) + poff);
        float q[4] = {h2lo(qr.x), h2hi(qr.x), h2lo(qr.y), h2hi(qr.y)};
        #pragma unroll
        for (int dr = 0; dr < 3; dr++) {
            int hh = h + dr - 1;
            bool rok = ((unsigned)hh < (unsigned)H);
            float m0 = kbv, m1 = kbv, m2 = kbv, m3 = kbv;
            if (rok) {
                uint2 kr = *(const uint2*)(kp + hh*W + wq);
                m0 = h2lo(kr.x); m1 = h2hi(kr.x);
                m2 = h2lo(kr.y); m3 = h2hi(kr.y);
            }
            float lf = __shfl_up_sync(0xffffffffu, m3, 1);
            if (lane == 0)  lf = kbv;
            float rt = __shfl_down_sync(0xffffffffu, m0, 1);
            if (lane == 31) rt = kbv;
            float val[6] = {lf, m0, m1, m2, m3, rt};
            #pragma unroll
            for (int dj = 0; dj < 3; dj++)
                #pragma unroll
                for (int p = 0; p < 4; p++)
                    sims[dr*3 + dj][p] = fmaf(q[p], val[p + dj], sims[dr*3 + dj][p]);
        }
    }

    #pragma unroll
    for (int o = 0; o < 9; o++)
        #pragma unroll
        for (int p = 0; p < 4; p++)
            att[cg][lane][o*4 + p] = sims[o][p];
    __syncthreads();

    #pragma unroll
    for (int o = 0; o < 9; o++) {
        #pragma unroll
        for (int p = 0; p < 4; p++) {
            float s = 0.f;
            #pragma unroll
            for (int gr = 0; gr < 8; gr++)
                s += att[gr][lane][o*4 + p];
            sims[o][p] = s;
        }
    }
    #pragma unroll
    for (int p = 0; p < 4; p++) {
        float mx = sims[0][p];
        #pragma unroll
        for (int o = 1; o < 9; o++) mx = fmaxf(mx, sims[o][p]);
        float se = 0.f;
        #pragma unroll
        for (int o = 0; o < 9; o++) { sims[o][p] = __expf(sims[o][p] - mx); se += sims[o][p]; }
        float inv = 1.f / se;
        #pragma unroll
        for (int o = 0; o < 9; o++) sims[o][p] *= inv;
    }

    #pragma unroll 2
    for (int ci = 0; ci < 16; ci++) {
        int c = c0 + ci;
        const __half* vp = g_v + bbase + ((size_t)c << 14);
        float vbv = __ldg(v_b + c);
        float o2[4] = {0.f, 0.f, 0.f, 0.f};
        #pragma unroll
        for (int dr = 0; dr < 3; dr++) {
            int hh = h + dr - 1;
            bool rok = ((unsigned)hh < (unsigned)H);
            float m0 = vbv, m1 = vbv, m2 = vbv, m3 = vbv;
            if (rok) {
                uint2 vr = *(const uint2*)(vp + hh*W + wq);
                m0 = h2lo(vr.x); m1 = h2hi(vr.x);
                m2 = h2lo(vr.y); m3 = h2hi(vr.y);
            }
            float lf = __shfl_up_sync(0xffffffffu, m3, 1);
            if (lane == 0)  lf = vbv;
            float rt = __shfl_down_sync(0xffffffffu, m0, 1);
            if (lane == 31) rt = vbv;
            float val[6] = {lf, m0, m1, m2, m3, rt};
            #pragma unroll
            for (int dj = 0; dj < 3; dj++)
                #pragma unroll
                for (int p = 0; p < 4; p++)
                    o2[p] = fmaf(sims[dr*3 + dj][p], val[p + dj], o2[p]);
        }
        size_t idx = bbase + ((size_t)c << 14) + poff;
        uint2 mraw = *(const uint2*)(g_m    + idx);
        uint2 oraw = *(const uint2*)(g_out1 + idx);
        float4 xv  = *(const float4*)(x     + idx);
        float mv0 = h2lo(mraw.x), mv1 = h2hi(mraw.x);
        float mv2 = h2lo(mraw.y), mv3 = h2hi(mraw.y);
        float o10 = h2lo(oraw.x), o11 = h2hi(oraw.x);
        float o12 = h2lo(oraw.y), o13 = h2hi(oraw.y);
        float4 ov;
        ov.x = xv.x + o10*mv0 + (1.f - mv0)*o2[0];
        ov.y = xv.y + o11*mv1 + (1.f - mv1)*o2[1];
        ov.z = xv.z + o12*mv2 + (1.f - mv2)*o2[2];
        ov.w = xv.w + o13*mv3 + (1.f - mv3)*o2[3];
        *(float4*)(out + idx) = ov;
    }
}

// ---------------- launch ----------------------------------------------------
extern "C" void kernel_launch(void* const* d_in, const int* in_sizes, int n_in,
                              void* d_out, int out_size)
{
    const float* x  = (const float*)d_in[0];
    const float* w1 = (const float*)d_in[1];
    const float* b1 = (const float*)d_in[2];
    const float* w2 = (const float*)d_in[3];
    const float* b2 = (const float*)d_in[4];
    const float* wm = (const float*)d_in[5];
    const float* bm = (const float*)d_in[6];
    const float* wq = (const float*)d_in[7];
    const float* bq = (const float*)d_in[8];
    const float* wk = (const float*)d_in[9];
    const float* bk = (const float*)d_in[10];
    const float* wv = (const float*)d_in[11];
    const float* bv = (const float*)d_in[12];
    float* out = (float*)d_out;

    cudaFuncSetAttribute(conv1_kernel,  cudaFuncAttributeMaxDynamicSharedMemorySize, CONV_SMEM);
    cudaFuncSetAttribute(conv2m_kernel, cudaFuncAttributeMaxDynamicSharedMemorySize, CONV_SMEM);

    pack_weights<<<216, 256>>>(w1, w2, wm, wq, wk, wv);

    dim3 gc(128, BATCH);
    conv1_kernel<<<gc, 256, CONV_SMEM>>>(x, b1);
    stats_kernel<<<BATCH*C, 512>>>();
    conv2m_kernel<<<gc, 256, CONV_SMEM>>>(b2, bm);
    conv_qkv<<<gc, 256>>>(bq, bk, bv);

    dim3 ga(H, BATCH);
    attn_kernel<<<ga, 256>>>(x, bk, bv, out);
}